// round 3
// baseline (speedup 1.0000x reference)
#include <cuda_runtime.h>
#include <cstdint>
#include <math.h>

#define NA 20000
#define NW 100000
#define HD 128
#define MAXE 760000   // max edges incl. self loops: infl = 600000 + 100000

// ---------------------------------------------------------------------------
// Static scratch (device globals are the sanctioned alloc-free scratch path)
// ---------------------------------------------------------------------------
struct Scratch {
    float ax[NA * HD];      // artist MLP out
    float hsA[NA * HD];     // hs buffer for artist-side src (GAT1 hs, GAT4 hs)
    float au[NA * HD];      // GAT3 out
    float ac[NA * HD];      // GAT4 out
    float wx[NW * HD];      // work MLP out
    float wtmp[NW * HD];    // work MLP hidden
    float wx1[NW * HD];     // GAT1 out
    float hsW[NW * HD];     // hs buffer for work-side src (GAT2 hs, GAT3 hs)
    float wx2[NW * HD];     // GAT2 out
    float h1[NA * 256];     // predictor hidden 1
    float h2[NA * HD];      // artist MLP hidden, then predictor hidden 2
    float s[NW];            // per-src attention scalar
    float dd[NW];           // per-dst attention scalar
    float u[HD];            // W @ a_d
    int cnt[NW];
    int indptr[NW + 1];
    int cursor[NW];
    int csr[MAXE];
    int bsum[1024];
};
__device__ Scratch g_S;

// ---------------------------------------------------------------------------
// GEMM: C[M,n] = act( A[M,K] @ B[K,n] (+ C if acc) (+ bias) )
// BM=BN=128, BK=32, 256 threads, 8x8 micro-tile per thread.
// ---------------------------------------------------------------------------
__global__ __launch_bounds__(256, 2)
void k_gemm(const float* __restrict__ A, const float* __restrict__ B,
            const float* __restrict__ bias, float* __restrict__ C,
            int M, int K, int n, int act, int acc)
{
    __shared__ float As[128][33];   // +1 pad: conflict-free scalar access
    __shared__ float Bs[32][128];

    const int tid = threadIdx.x;
    const int tx = tid & 15;        // 0..15 -> col group
    const int ty = tid >> 4;        // 0..15 -> row group
    const int row0 = blockIdx.x * 128;
    const int col0 = blockIdx.y * 128;

    float accr[8][8];
#pragma unroll
    for (int i = 0; i < 8; i++)
#pragma unroll
        for (int j = 0; j < 8; j++) accr[i][j] = 0.0f;

    const int ktiles = K >> 5;
    for (int kt = 0; kt < ktiles; kt++) {
        // load A tile: 128 rows x 32 k, float4 per thread x4
#pragma unroll
        for (int i = 0; i < 4; i++) {
            int idx = tid + i * 256;          // 0..1023
            int r = idx >> 3;                 // 0..127
            int kq = idx & 7;                 // 0..7 (float4 slot)
            float4 v = make_float4(0.f, 0.f, 0.f, 0.f);
            int gr = row0 + r;
            if (gr < M)
                v = *(const float4*)(A + (size_t)gr * K + (kt << 5) + (kq << 2));
            As[r][kq * 4 + 0] = v.x; As[r][kq * 4 + 1] = v.y;
            As[r][kq * 4 + 2] = v.z; As[r][kq * 4 + 3] = v.w;
        }
        // load B tile: 32 k x 128 n
#pragma unroll
        for (int i = 0; i < 4; i++) {
            int idx = tid + i * 256;
            int k = idx >> 5;                 // 0..31
            int n4 = idx & 31;                // 0..31
            float4 v = *(const float4*)(B + (size_t)((kt << 5) + k) * n + col0 + (n4 << 2));
            *(float4*)&Bs[k][n4 << 2] = v;
        }
        __syncthreads();

#pragma unroll 8
        for (int k = 0; k < 32; k++) {
            float af[8], bf[8];
#pragma unroll
            for (int i = 0; i < 8; i++) af[i] = As[ty * 8 + i][k];
#pragma unroll
            for (int j = 0; j < 8; j++) bf[j] = Bs[k][tx * 8 + j];
#pragma unroll
            for (int i = 0; i < 8; i++)
#pragma unroll
                for (int j = 0; j < 8; j++)
                    accr[i][j] = fmaf(af[i], bf[j], accr[i][j]);
        }
        __syncthreads();
    }

    // epilogue
#pragma unroll
    for (int i = 0; i < 8; i++) {
        int r = row0 + ty * 8 + i;
        if (r >= M) continue;
        float* cp = C + (size_t)r * n + col0 + tx * 8;
#pragma unroll
        for (int jj = 0; jj < 8; jj += 4) {
            float4 v = make_float4(accr[i][jj], accr[i][jj + 1],
                                   accr[i][jj + 2], accr[i][jj + 3]);
            if (acc) {
                float4 o = *(float4*)(cp + jj);
                v.x += o.x; v.y += o.y; v.z += o.z; v.w += o.w;
            }
            if (bias) {
                float4 b = *(const float4*)(bias + col0 + tx * 8 + jj);
                v.x += b.x; v.y += b.y; v.z += b.z; v.w += b.w;
            }
            if (act == 1) {
                v.x = fmaxf(v.x, 0.f); v.y = fmaxf(v.y, 0.f);
                v.z = fmaxf(v.z, 0.f); v.w = fmaxf(v.w, 0.f);
            }
            *(float4*)(cp + jj) = v;
        }
    }
}

// ---------------------------------------------------------------------------
// u[k] = sum_c W[k,c] * v[c]   (tiny: 1 block, 128 threads)
// ---------------------------------------------------------------------------
__global__ void k_matvec(const float* __restrict__ W, const float* __restrict__ v,
                         float* __restrict__ u)
{
    int k = threadIdx.x;
    float sm = 0.f;
#pragma unroll 8
    for (int c = 0; c < HD; c++) sm = fmaf(W[k * HD + c], v[c], sm);
    u[k] = sm;
}

// ---------------------------------------------------------------------------
// out[i] = dot(X[i,:], v)   one warp per row
// ---------------------------------------------------------------------------
__global__ void k_rowdot(const float* __restrict__ X, const float* __restrict__ v,
                         float* __restrict__ out, int nrows)
{
    int w = (blockIdx.x * blockDim.x + threadIdx.x) >> 5;
    int lane = threadIdx.x & 31;
    if (w >= nrows) return;
    float4 x = ((const float4*)X)[(size_t)w * 32 + lane];
    float4 vv = ((const float4*)v)[lane];
    float sm = x.x * vv.x + x.y * vv.y + x.z * vv.z + x.w * vv.w;
#pragma unroll
    for (int off = 16; off; off >>= 1) sm += __shfl_xor_sync(0xffffffffu, sm, off);
    if (lane == 0) out[w] = sm;
}

// ---------------------------------------------------------------------------
// CSR build
// ---------------------------------------------------------------------------
__global__ void k_zero(int* p, int nv)
{
    int i = blockIdx.x * blockDim.x + threadIdx.x;
    if (i < nv) p[i] = 0;
}

__global__ void k_count(const int* __restrict__ dst, int E, int nloop, int* __restrict__ cnt)
{
    int i = blockIdx.x * blockDim.x + threadIdx.x;
    if (i < E) atomicAdd(&cnt[dst[i]], 1);
    else if (i < E + nloop) atomicAdd(&cnt[i - E], 1);
}

__global__ void k_scan_block(const int* __restrict__ in, int* __restrict__ out,
                             int* __restrict__ bsums, int nv)
{
    __shared__ int sh[1024];
    int i = blockIdx.x * 1024 + threadIdx.x;
    int v = (i < nv) ? in[i] : 0;
    sh[threadIdx.x] = v;
    __syncthreads();
    for (int off = 1; off < 1024; off <<= 1) {
        int t = (threadIdx.x >= off) ? sh[threadIdx.x - off] : 0;
        __syncthreads();
        sh[threadIdx.x] += t;
        __syncthreads();
    }
    if (i < nv) out[i] = sh[threadIdx.x] - v;   // exclusive
    if (threadIdx.x == 1023) bsums[blockIdx.x] = sh[1023];
}

__global__ void k_scan_bsums(int* __restrict__ bsums, int nb, int* __restrict__ total_out)
{
    __shared__ int sh[1024];
    int i = threadIdx.x;
    int v = (i < nb) ? bsums[i] : 0;
    sh[i] = v;
    __syncthreads();
    for (int off = 1; off < 1024; off <<= 1) {
        int t = (i >= off) ? sh[i - off] : 0;
        __syncthreads();
        sh[i] += t;
        __syncthreads();
    }
    if (i < nb) bsums[i] = sh[i] - v;           // exclusive
    if (i == nb - 1) *total_out = sh[i];        // grand total -> indptr[n]
}

__global__ void k_scan_add(int* __restrict__ indptr, int* __restrict__ cursor,
                           const int* __restrict__ bsums, int nv)
{
    int i = blockIdx.x * blockDim.x + threadIdx.x;
    if (i < nv) {
        int v = indptr[i] + bsums[i >> 10];
        indptr[i] = v;
        cursor[i] = v;
    }
}

__global__ void k_fill(const int* __restrict__ src, const int* __restrict__ dst,
                       int E, int nloop, int* __restrict__ cursor, int* __restrict__ csr)
{
    int i = blockIdx.x * blockDim.x + threadIdx.x;
    if (i < E) {
        int p = atomicAdd(&cursor[dst[i]], 1);
        csr[p] = src[i];
    } else if (i < E + nloop) {
        int j = i - E;
        int p = atomicAdd(&cursor[j], 1);
        csr[p] = j;
    }
}

// ---------------------------------------------------------------------------
// GAT aggregation: one warp per dst node. Two passes over in-edges:
//   pass1: warp-strided max of leaky_relu(s[src]+d[dst])
//   pass2: exp-weighted gather of hs[src] rows (coalesced float4 per lane)
// out = act( sum/denom + bias ).  act: 0=none, 1=elu
// ---------------------------------------------------------------------------
__global__ void k_gat(const int* __restrict__ indptr, const int* __restrict__ csr,
                      const float* __restrict__ hs, const float* __restrict__ s,
                      const float* __restrict__ d, const float* __restrict__ bias,
                      float* __restrict__ out, int ndst, int act)
{
    int w = (blockIdx.x * blockDim.x + threadIdx.x) >> 5;
    int lane = threadIdx.x & 31;
    if (w >= ndst) return;

    int beg = indptr[w], end = indptr[w + 1];
    float4 b4 = ((const float4*)bias)[lane];
    float4 o;

    if (end > beg) {
        float dj = d[w];
        float m = -3.0e38f;
        for (int e = beg + lane; e < end; e += 32) {
            float l = s[csr[e]] + dj;
            l = (l > 0.f) ? l : 0.2f * l;
            m = fmaxf(m, l);
        }
#pragma unroll
        for (int off = 16; off; off >>= 1)
            m = fmaxf(m, __shfl_xor_sync(0xffffffffu, m, off));

        float denom = 0.f;
        float4 acc = make_float4(0.f, 0.f, 0.f, 0.f);
        for (int e = beg; e < end; e++) {
            int sn = csr[e];
            float l = s[sn] + dj;
            l = (l > 0.f) ? l : 0.2f * l;
            float wt = __expf(l - m);
            denom += wt;
            float4 hv = ((const float4*)hs)[(size_t)sn * 32 + lane];
            acc.x = fmaf(wt, hv.x, acc.x);
            acc.y = fmaf(wt, hv.y, acc.y);
            acc.z = fmaf(wt, hv.z, acc.z);
            acc.w = fmaf(wt, hv.w, acc.w);
        }
        float inv = 1.0f / denom;
        o.x = fmaf(acc.x, inv, b4.x);
        o.y = fmaf(acc.y, inv, b4.y);
        o.z = fmaf(acc.z, inv, b4.z);
        o.w = fmaf(acc.w, inv, b4.w);
    } else {
        o = b4;   // empty neighborhood: segment_sum = 0, out = bias
    }

    if (act == 1) {
        o.x = (o.x > 0.f) ? o.x : expm1f(o.x);
        o.y = (o.y > 0.f) ? o.y : expm1f(o.y);
        o.z = (o.z > 0.f) ? o.z : expm1f(o.z);
        o.w = (o.w > 0.f) ? o.w : expm1f(o.w);
    }
    ((float4*)out)[(size_t)w * 32 + lane] = o;
}

// ---------------------------------------------------------------------------
// final: out[i] = dot(h2[i,:], w3) + b3
// ---------------------------------------------------------------------------
__global__ void k_pred(const float* __restrict__ h2, const float* __restrict__ w3,
                       const float* __restrict__ b3, float* __restrict__ out, int nrows)
{
    int w = (blockIdx.x * blockDim.x + threadIdx.x) >> 5;
    int lane = threadIdx.x & 31;
    if (w >= nrows) return;
    float4 x = ((const float4*)h2)[(size_t)w * 32 + lane];
    float4 vv = ((const float4*)w3)[lane];
    float sm = x.x * vv.x + x.y * vv.y + x.z * vv.z + x.w * vv.w;
#pragma unroll
    for (int off = 16; off; off >>= 1) sm += __shfl_xor_sync(0xffffffffu, sm, off);
    if (lane == 0) out[w] = sm + b3[0];
}

// ---------------------------------------------------------------------------
static inline int ceil_div(int a, int b) { return (a + b - 1) / b; }

extern "C" void kernel_launch(void* const* d_in, const int* in_sizes, int n_in,
                              void* d_out, int out_size)
{
    Scratch* S;
    cudaGetSymbolAddress((void**)&S, g_S);

    const float* af   = (const float*)d_in[0];
    const float* wf   = (const float*)d_in[1];
    const float* a_w1 = (const float*)d_in[2];
    const float* a_b1 = (const float*)d_in[3];
    const float* a_w2 = (const float*)d_in[4];
    const float* a_b2 = (const float*)d_in[5];
    const float* w_w1 = (const float*)d_in[6];
    const float* w_b1 = (const float*)d_in[7];
    const float* w_w2 = (const float*)d_in[8];
    const float* w_b2 = (const float*)d_in[9];
    const float* cr_W = (const float*)d_in[10];
    const float* cr_b = (const float*)d_in[11];
    const float* cr_as = (const float*)d_in[12];
    const float* cr_ad = (const float*)d_in[13];
    const float* in_W = (const float*)d_in[14];
    const float* in_b = (const float*)d_in[15];
    const float* in_as = (const float*)d_in[16];
    const float* in_ad = (const float*)d_in[17];
    const float* co_W = (const float*)d_in[18];
    const float* co_b = (const float*)d_in[19];
    const float* co_as = (const float*)d_in[20];
    const float* co_ad = (const float*)d_in[21];
    const float* p_w1 = (const float*)d_in[22];
    const float* p_b1 = (const float*)d_in[23];
    const float* p_w2 = (const float*)d_in[24];
    const float* p_b2 = (const float*)d_in[25];
    const float* p_w3 = (const float*)d_in[26];
    const float* p_b3 = (const float*)d_in[27];
    const int* e_cr = (const int*)d_in[28]; int Ecr = in_sizes[28] / 2;
    const int* e_cb = (const int*)d_in[29]; int Ecb = in_sizes[29] / 2;
    const int* e_in = (const int*)d_in[30]; int Ein = in_sizes[30] / 2;
    const int* e_co = (const int*)d_in[31]; int Eco = in_sizes[31] / 2;
    float* out = (float*)d_out;

    auto gemm = [&](const float* A, int M, int K, const float* B, const float* bias,
                    float* C, int n, int act, int acc) {
        dim3 g(ceil_div(M, 128), n / 128);
        k_gemm<<<g, 256>>>(A, B, bias, C, M, K, n, act, acc);
    };

    auto build_csr = [&](const int* src, const int* dst, int E, int nloop, int ndst) {
        k_zero<<<ceil_div(ndst, 256), 256>>>(S->cnt, ndst);
        k_count<<<ceil_div(E + nloop, 256), 256>>>(dst, E, nloop, S->cnt);
        int nb = ceil_div(ndst, 1024);
        k_scan_block<<<nb, 1024>>>(S->cnt, S->indptr, S->bsum, ndst);
        k_scan_bsums<<<1, 1024>>>(S->bsum, nb, S->indptr + ndst);
        k_scan_add<<<ceil_div(ndst, 256), 256>>>(S->indptr, S->cursor, S->bsum, ndst);
        k_fill<<<ceil_div(E + nloop, 256), 256>>>(src, dst, E, nloop, S->cursor, S->csr);
    };

    auto gat = [&](const float* hs, const float* bias, float* o, int ndst, int act) {
        k_gat<<<ceil_div(ndst, 8), 256>>>(S->indptr, S->csr, hs, S->s, S->dd,
                                          bias, o, ndst, act);
    };
    auto rowdot = [&](const float* X, const float* v, float* o, int nrows) {
        k_rowdot<<<ceil_div(nrows, 8), 256>>>(X, v, o, nrows);
    };

    // ---- node MLPs ----
    gemm(af, NA, 64, a_w1, a_b1, S->h2, 128, 1, 0);        // artist hidden (relu)
    gemm(S->h2, NA, 128, a_w2, a_b2, S->ax, 128, 0, 0);    // ax
    gemm(wf, NW, 128, w_w1, w_b1, S->wtmp, 128, 1, 0);     // work hidden (relu)
    gemm(S->wtmp, NW, 128, w_w2, w_b2, S->wx, 128, 0, 0);  // wx

    // ---- GAT1: creates (artist -> work), ELU ----
    gemm(S->ax, NA, 128, cr_W, nullptr, S->hsA, 128, 0, 0);    // hs = ax @ cr_W
    k_matvec<<<1, 128>>>(cr_W, cr_ad, S->u);                    // u = cr_W @ a_d
    rowdot(S->hsA, cr_as, S->s, NA);                            // s[src]
    rowdot(S->wx, S->u, S->dd, NW);                             // d[dst]
    build_csr(e_cr, e_cr + Ecr, Ecr, NA, NW);                   // loops: i<NA
    gat(S->hsA, cr_b, S->wx1, NW, 1);

    // ---- GAT2: infl (work -> work), ELU ----
    gemm(S->wx1, NW, 128, in_W, nullptr, S->hsW, 128, 0, 0);
    k_matvec<<<1, 128>>>(in_W, in_ad, S->u);
    rowdot(S->hsW, in_as, S->s, NW);
    rowdot(S->wx1, S->u, S->dd, NW);
    build_csr(e_in, e_in + Ein, Ein, NW, NW);
    gat(S->hsW, in_b, S->wx2, NW, 1);

    // ---- GAT3: created_by (work -> artist), no activation ----
    gemm(S->wx2, NW, 128, cr_W, nullptr, S->hsW, 128, 0, 0);   // hs = wx2 @ cr_W
    k_matvec<<<1, 128>>>(cr_W, cr_ad, S->u);
    rowdot(S->hsW, cr_as, S->s, NW);
    rowdot(S->ax, S->u, S->dd, NA);                             // dst = original ax
    build_csr(e_cb, e_cb + Ecb, Ecb, NA, NA);                   // loops: min(NW,NA)=NA
    gat(S->hsW, cr_b, S->au, NA, 0);

    // ---- GAT4: collab (artist -> artist), ELU ----
    gemm(S->au, NA, 128, co_W, nullptr, S->hsA, 128, 0, 0);
    k_matvec<<<1, 128>>>(co_W, co_ad, S->u);
    rowdot(S->hsA, co_as, S->s, NA);
    rowdot(S->au, S->u, S->dd, NA);
    build_csr(e_co, e_co + Eco, Eco, NA, NA);
    gat(S->hsA, co_b, S->ac, NA, 1);

    // ---- predictor ----
    // h1 = relu([au, ac] @ p_w1 + b1)  -> split: au @ top-half + ac @ bottom-half
    gemm(S->au, NA, 128, p_w1, p_b1, S->h1, 256, 0, 0);
    gemm(S->ac, NA, 128, p_w1 + 128 * 256, nullptr, S->h1, 256, 1, 1);
    // h2 = relu(h1 @ p_w2 + b2)
    gemm(S->h1, NA, 256, p_w2, p_b2, S->h2, 128, 1, 0);
    // out = h2 @ p_w3 + b3
    k_pred<<<ceil_div(NA, 8), 256>>>(S->h2, p_w3, p_b3, out, NA);
}

// round 4
// speedup vs baseline: 1.1156x; 1.1156x over previous
#include <cuda_runtime.h>
#include <cstdint>
#include <math.h>

#define NA 20000
#define NW 100000
#define HD 128
#define MAXE 760000   // max edges incl. self loops: infl = 600000 + 100000

// ---------------------------------------------------------------------------
// Static scratch
// ---------------------------------------------------------------------------
struct Scratch {
    float ax[NA * HD];
    float hsA[NA * HD];
    float au[NA * HD];
    float ac[NA * HD];
    float wx[NW * HD];
    float wtmp[NW * HD];
    float wx1[NW * HD];
    float hsW[NW * HD];
    float wx2[NW * HD];
    float h1[NA * 256];
    float h2[NA * HD];
    float s[NW];
    float ddW[NW];
    float dd2[NW];
    float ddA[NA];
    float dd3[NA];
    float u_cr[HD];
    float u_in[HD];
    float u_co[HD];
    int cnt[NW];
    int indptr[NW + 1];
    int cursor[NW];
    int csr[MAXE];
    int bsum[1024];
};
__device__ Scratch g_S;

__device__ __forceinline__ void cp_async16(uint32_t dst, const void* src) {
    asm volatile("cp.async.cg.shared.global [%0], [%1], 16;\n" :: "r"(dst), "l"(src));
}
__device__ __forceinline__ void cp_commit() {
    asm volatile("cp.async.commit_group;\n");
}
__device__ __forceinline__ void cp_wait0() {
    asm volatile("cp.async.wait_group 0;\n");
}

// ---------------------------------------------------------------------------
// Pipelined GEMM: C[M,n] = act( A[M,K] @ B[K,n] (+C if acc) (+bias) )
// BM = 16*TM, BN=128, BK=32, 256 threads, TMx8 micro-tile.
// A smem stored TRANSPOSED (At[k][r], pad 4) -> vectorized af loads.
// B via cp.async double-buffer; A via register prefetch + STS.
// Optional fused row-dot: sout[r] = dot(C_row_final, sv)  (requires gridDim.y==1)
// ---------------------------------------------------------------------------
template<int TM>
__global__ __launch_bounds__(256, 2)
void k_gemm(const float* __restrict__ A, const float* __restrict__ B,
            const float* __restrict__ bias, float* __restrict__ C,
            const float* __restrict__ sv, float* __restrict__ sout,
            int M, int K, int n, int act, int acc)
{
    constexpr int BM = TM * 16;
    constexpr int AS = BM + 4;                  // padded row (16B multiple)
    constexpr int AIT = (BM * 32) / (256 * 4);  // float4 A loads / thread / tile
    extern __shared__ float sh[];
    float* At = sh;                     // [2][32][AS]
    float* Bs = sh + 2 * 32 * AS;       // [2][32][128]

    const int tid = threadIdx.x;
    const int tx = tid & 15;
    const int ty = tid >> 4;
    const int row0 = blockIdx.x * BM;
    const int col0 = blockIdx.y * 128;

    uint32_t Bs_s = (uint32_t)__cvta_generic_to_shared(Bs);

    float acr[TM][8];
#pragma unroll
    for (int i = 0; i < TM; i++)
#pragma unroll
        for (int j = 0; j < 8; j++) acr[i][j] = 0.0f;

    float4 pref[AIT];

    auto ldgA = [&](int kt) {
#pragma unroll
        for (int it = 0; it < AIT; it++) {
            int idx = tid + it * 256;
            int r = idx >> 3, kq = idx & 7;
            int gr = row0 + r;
            pref[it] = (gr < M)
                ? *(const float4*)(A + (size_t)gr * K + (kt << 5) + (kq << 2))
                : make_float4(0.f, 0.f, 0.f, 0.f);
        }
    };
    auto stsA = [&](int b) {
#pragma unroll
        for (int it = 0; it < AIT; it++) {
            int idx = tid + it * 256;
            int r = idx >> 3, kq = idx & 7;
            float* base = At + b * (32 * AS) + (kq * 4) * AS + r;
            base[0 * AS] = pref[it].x;
            base[1 * AS] = pref[it].y;
            base[2 * AS] = pref[it].z;
            base[3 * AS] = pref[it].w;
        }
    };
    auto cpB = [&](int kt, int b) {
#pragma unroll
        for (int it = 0; it < 4; it++) {
            int idx = tid + it * 256;
            int k = idx >> 5, c4 = idx & 31;
            uint32_t dst = Bs_s + (uint32_t)(((b * 32 + k) * 128 + (c4 << 2)) * 4);
            cp_async16(dst, B + (size_t)((kt << 5) + k) * n + col0 + (c4 << 2));
        }
        cp_commit();
    };
    auto compute = [&](int b) {
        const float* Atb = At + b * (32 * AS);
        const float* Bsb = Bs + b * (32 * 128);
#pragma unroll
        for (int k = 0; k < 32; k++) {
            float af[TM], bf[8];
#pragma unroll
            for (int q = 0; q < TM / 4; q++)
                *(float4*)&af[q * 4] = *(const float4*)(Atb + k * AS + ty * TM + q * 4);
            *(float4*)&bf[0] = *(const float4*)(Bsb + k * 128 + tx * 8);
            *(float4*)&bf[4] = *(const float4*)(Bsb + k * 128 + tx * 8 + 4);
#pragma unroll
            for (int i = 0; i < TM; i++)
#pragma unroll
                for (int j = 0; j < 8; j++)
                    acr[i][j] = fmaf(af[i], bf[j], acr[i][j]);
        }
    };

    const int ktiles = K >> 5;

    // prologue
    ldgA(0);
    cpB(0, 0);
    stsA(0);
    cp_wait0();
    __syncthreads();

    int buf = 0;
    for (int kt = 0; kt < ktiles; kt++) {
        bool more = (kt + 1 < ktiles);
        if (more) { ldgA(kt + 1); cpB(kt + 1, buf ^ 1); }
        compute(buf);
        if (more) {
            stsA(buf ^ 1);
            cp_wait0();
            __syncthreads();
            buf ^= 1;
        }
    }

    // epilogue (no early returns: shuffles need full warp)
#pragma unroll
    for (int i = 0; i < TM; i++) {
        int r = row0 + ty * TM + i;
        bool ok = (r < M);
        float* cp = C + (size_t)r * n + col0 + tx * 8;
        float part = 0.f;
#pragma unroll
        for (int jj = 0; jj < 8; jj += 4) {
            float4 v = make_float4(acr[i][jj], acr[i][jj + 1],
                                   acr[i][jj + 2], acr[i][jj + 3]);
            if (acc && ok) {
                float4 o = *(float4*)(cp + jj);
                v.x += o.x; v.y += o.y; v.z += o.z; v.w += o.w;
            }
            if (bias) {
                float4 b = *(const float4*)(bias + col0 + tx * 8 + jj);
                v.x += b.x; v.y += b.y; v.z += b.z; v.w += b.w;
            }
            if (act == 1) {
                v.x = fmaxf(v.x, 0.f); v.y = fmaxf(v.y, 0.f);
                v.z = fmaxf(v.z, 0.f); v.w = fmaxf(v.w, 0.f);
            }
            if (ok) *(float4*)(cp + jj) = v;
            if (sv) {
                float4 s4 = *(const float4*)(sv + col0 + tx * 8 + jj);
                part += v.x * s4.x + v.y * s4.y + v.z * s4.z + v.w * s4.w;
            }
        }
        if (sv) {
            part += __shfl_xor_sync(0xffffffffu, part, 1);
            part += __shfl_xor_sync(0xffffffffu, part, 2);
            part += __shfl_xor_sync(0xffffffffu, part, 4);
            part += __shfl_xor_sync(0xffffffffu, part, 8);
            if (ok && tx == 0) sout[r] = part;
        }
    }
}

// ---------------------------------------------------------------------------
// u[k] = sum_c W[k,c] * v[c]
// ---------------------------------------------------------------------------
__global__ void k_matvec(const float* __restrict__ W, const float* __restrict__ v,
                         float* __restrict__ u)
{
    int k = threadIdx.x;
    float sm = 0.f;
#pragma unroll 8
    for (int c = 0; c < HD; c++) sm = fmaf(W[k * HD + c], v[c], sm);
    u[k] = sm;
}

// ---------------------------------------------------------------------------
// CSR build
// ---------------------------------------------------------------------------
__global__ void k_zero(int* p, int nv)
{
    int i = blockIdx.x * blockDim.x + threadIdx.x;
    if (i < nv) p[i] = 0;
}

__global__ void k_count(const int* __restrict__ dst, int E, int nloop, int* __restrict__ cnt)
{
    int i = blockIdx.x * blockDim.x + threadIdx.x;
    if (i < E) atomicAdd(&cnt[dst[i]], 1);
    else if (i < E + nloop) atomicAdd(&cnt[i - E], 1);
}

__global__ void k_scan_block(const int* __restrict__ in, int* __restrict__ out,
                             int* __restrict__ bsums, int nv)
{
    __shared__ int sh[1024];
    int i = blockIdx.x * 1024 + threadIdx.x;
    int v = (i < nv) ? in[i] : 0;
    sh[threadIdx.x] = v;
    __syncthreads();
    for (int off = 1; off < 1024; off <<= 1) {
        int t = (threadIdx.x >= off) ? sh[threadIdx.x - off] : 0;
        __syncthreads();
        sh[threadIdx.x] += t;
        __syncthreads();
    }
    if (i < nv) out[i] = sh[threadIdx.x] - v;
    if (threadIdx.x == 1023) bsums[blockIdx.x] = sh[1023];
}

__global__ void k_scan_bsums(int* __restrict__ bsums, int nb, int* __restrict__ total_out)
{
    __shared__ int sh[1024];
    int i = threadIdx.x;
    int v = (i < nb) ? bsums[i] : 0;
    sh[i] = v;
    __syncthreads();
    for (int off = 1; off < 1024; off <<= 1) {
        int t = (i >= off) ? sh[i - off] : 0;
        __syncthreads();
        sh[i] += t;
        __syncthreads();
    }
    if (i < nb) bsums[i] = sh[i] - v;
    if (i == nb - 1) *total_out = sh[i];
}

__global__ void k_scan_add(int* __restrict__ indptr, int* __restrict__ cursor,
                           const int* __restrict__ bsums, int nv)
{
    int i = blockIdx.x * blockDim.x + threadIdx.x;
    if (i < nv) {
        int v = indptr[i] + bsums[i >> 10];
        indptr[i] = v;
        cursor[i] = v;
    }
}

__global__ void k_fill(const int* __restrict__ src, const int* __restrict__ dst,
                       int E, int nloop, int* __restrict__ cursor, int* __restrict__ csr)
{
    int i = blockIdx.x * blockDim.x + threadIdx.x;
    if (i < E) {
        int p = atomicAdd(&cursor[dst[i]], 1);
        csr[p] = src[i];
    } else if (i < E + nloop) {
        int j = i - E;
        int p = atomicAdd(&cursor[j], 1);
        csr[p] = j;
    }
}

// ---------------------------------------------------------------------------
// GAT aggregation (one warp / dst node) with optional fused next-layer d-dot:
//   dd_out[w] = dot(out_row, unext)
// ---------------------------------------------------------------------------
__global__ void k_gat(const int* __restrict__ indptr, const int* __restrict__ csr,
                      const float* __restrict__ hs, const float* __restrict__ s,
                      const float* __restrict__ d, const float* __restrict__ bias,
                      float* __restrict__ out, int ndst, int act,
                      const float* __restrict__ unext, float* __restrict__ dd_out)
{
    int w = (blockIdx.x * blockDim.x + threadIdx.x) >> 5;
    int lane = threadIdx.x & 31;
    if (w >= ndst) return;

    int beg = indptr[w], end = indptr[w + 1];
    float4 b4 = ((const float4*)bias)[lane];
    float4 o;

    if (end > beg) {
        float dj = d[w];
        float m = -3.0e38f;
        for (int e = beg + lane; e < end; e += 32) {
            float l = s[csr[e]] + dj;
            l = (l > 0.f) ? l : 0.2f * l;
            m = fmaxf(m, l);
        }
#pragma unroll
        for (int off = 16; off; off >>= 1)
            m = fmaxf(m, __shfl_xor_sync(0xffffffffu, m, off));

        float denom = 0.f;
        float4 acc = make_float4(0.f, 0.f, 0.f, 0.f);
        for (int e = beg; e < end; e++) {
            int sn = csr[e];
            float l = s[sn] + dj;
            l = (l > 0.f) ? l : 0.2f * l;
            float wt = __expf(l - m);
            denom += wt;
            float4 hv = ((const float4*)hs)[(size_t)sn * 32 + lane];
            acc.x = fmaf(wt, hv.x, acc.x);
            acc.y = fmaf(wt, hv.y, acc.y);
            acc.z = fmaf(wt, hv.z, acc.z);
            acc.w = fmaf(wt, hv.w, acc.w);
        }
        float inv = 1.0f / denom;
        o.x = fmaf(acc.x, inv, b4.x);
        o.y = fmaf(acc.y, inv, b4.y);
        o.z = fmaf(acc.z, inv, b4.z);
        o.w = fmaf(acc.w, inv, b4.w);
    } else {
        o = b4;
    }

    if (act == 1) {
        o.x = (o.x > 0.f) ? o.x : expm1f(o.x);
        o.y = (o.y > 0.f) ? o.y : expm1f(o.y);
        o.z = (o.z > 0.f) ? o.z : expm1f(o.z);
        o.w = (o.w > 0.f) ? o.w : expm1f(o.w);
    }
    ((float4*)out)[(size_t)w * 32 + lane] = o;

    if (dd_out) {
        float4 u4 = ((const float4*)unext)[lane];
        float p = o.x * u4.x + o.y * u4.y + o.z * u4.z + o.w * u4.w;
#pragma unroll
        for (int off = 16; off; off >>= 1) p += __shfl_xor_sync(0xffffffffu, p, off);
        if (lane == 0) dd_out[w] = p;
    }
}

// ---------------------------------------------------------------------------
// final: out[i] = dot(h2[i,:], w3) + b3
// ---------------------------------------------------------------------------
__global__ void k_pred(const float* __restrict__ h2, const float* __restrict__ w3,
                       const float* __restrict__ b3, float* __restrict__ out, int nrows)
{
    int w = (blockIdx.x * blockDim.x + threadIdx.x) >> 5;
    int lane = threadIdx.x & 31;
    if (w >= nrows) return;
    float4 x = ((const float4*)h2)[(size_t)w * 32 + lane];
    float4 vv = ((const float4*)w3)[lane];
    float sm = x.x * vv.x + x.y * vv.y + x.z * vv.z + x.w * vv.w;
#pragma unroll
    for (int off = 16; off; off >>= 1) sm += __shfl_xor_sync(0xffffffffu, sm, off);
    if (lane == 0) out[w] = sm + b3[0];
}

// ---------------------------------------------------------------------------
static inline int ceil_div(int a, int b) { return (a + b - 1) / b; }

static const int SMEM8 = (2 * 32 * (128 + 4) + 2 * 32 * 128) * 4;  // 66560
static const int SMEM4 = (2 * 32 * (64 + 4) + 2 * 32 * 128) * 4;   // 50176

extern "C" void kernel_launch(void* const* d_in, const int* in_sizes, int n_in,
                              void* d_out, int out_size)
{
    Scratch* S;
    cudaGetSymbolAddress((void**)&S, g_S);

    cudaFuncSetAttribute(k_gemm<8>, cudaFuncAttributeMaxDynamicSharedMemorySize, SMEM8);
    cudaFuncSetAttribute(k_gemm<4>, cudaFuncAttributeMaxDynamicSharedMemorySize, SMEM4);

    const float* af   = (const float*)d_in[0];
    const float* wf   = (const float*)d_in[1];
    const float* a_w1 = (const float*)d_in[2];
    const float* a_b1 = (const float*)d_in[3];
    const float* a_w2 = (const float*)d_in[4];
    const float* a_b2 = (const float*)d_in[5];
    const float* w_w1 = (const float*)d_in[6];
    const float* w_b1 = (const float*)d_in[7];
    const float* w_w2 = (const float*)d_in[8];
    const float* w_b2 = (const float*)d_in[9];
    const float* cr_W = (const float*)d_in[10];
    const float* cr_b = (const float*)d_in[11];
    const float* cr_as = (const float*)d_in[12];
    const float* cr_ad = (const float*)d_in[13];
    const float* in_W = (const float*)d_in[14];
    const float* in_b = (const float*)d_in[15];
    const float* in_as = (const float*)d_in[16];
    const float* in_ad = (const float*)d_in[17];
    const float* co_W = (const float*)d_in[18];
    const float* co_b = (const float*)d_in[19];
    const float* co_as = (const float*)d_in[20];
    const float* co_ad = (const float*)d_in[21];
    const float* p_w1 = (const float*)d_in[22];
    const float* p_b1 = (const float*)d_in[23];
    const float* p_w2 = (const float*)d_in[24];
    const float* p_b2 = (const float*)d_in[25];
    const float* p_w3 = (const float*)d_in[26];
    const float* p_b3 = (const float*)d_in[27];
    const int* e_cr = (const int*)d_in[28]; int Ecr = in_sizes[28] / 2;
    const int* e_cb = (const int*)d_in[29]; int Ecb = in_sizes[29] / 2;
    const int* e_in = (const int*)d_in[30]; int Ein = in_sizes[30] / 2;
    const int* e_co = (const int*)d_in[31]; int Eco = in_sizes[31] / 2;
    float* out = (float*)d_out;

    auto gemm = [&](const float* A, int M, int K, const float* B, const float* bias,
                    float* C, int n, int act, int acc,
                    const float* sv, float* sout) {
        if (M > 32000) {
            dim3 g(ceil_div(M, 128), n / 128);
            k_gemm<8><<<g, 256, SMEM8>>>(A, B, bias, C, sv, sout, M, K, n, act, acc);
        } else {
            dim3 g(ceil_div(M, 64), n / 128);
            k_gemm<4><<<g, 256, SMEM4>>>(A, B, bias, C, sv, sout, M, K, n, act, acc);
        }
    };

    auto build_csr = [&](const int* src, const int* dst, int E, int nloop, int ndst) {
        k_zero<<<ceil_div(ndst, 256), 256>>>(S->cnt, ndst);
        k_count<<<ceil_div(E + nloop, 256), 256>>>(dst, E, nloop, S->cnt);
        int nb = ceil_div(ndst, 1024);
        k_scan_block<<<nb, 1024>>>(S->cnt, S->indptr, S->bsum, ndst);
        k_scan_bsums<<<1, 1024>>>(S->bsum, nb, S->indptr + ndst);
        k_scan_add<<<ceil_div(ndst, 256), 256>>>(S->indptr, S->cursor, S->bsum, ndst);
        k_fill<<<ceil_div(E + nloop, 256), 256>>>(src, dst, E, nloop, S->cursor, S->csr);
    };

    auto gat = [&](const float* hs, const float* d, const float* bias, float* o,
                   int ndst, int act, const float* unext, float* dd_out) {
        k_gat<<<ceil_div(ndst, 8), 256>>>(S->indptr, S->csr, hs, S->s, d,
                                          bias, o, ndst, act, unext, dd_out);
    };

    // ---- u vectors (needed by fused d-dots below) ----
    k_matvec<<<1, 128>>>(cr_W, cr_ad, S->u_cr);
    k_matvec<<<1, 128>>>(in_W, in_ad, S->u_in);
    k_matvec<<<1, 128>>>(co_W, co_ad, S->u_co);

    // ---- node MLPs (fused d-dots: ddA = ax.u_cr, ddW = wx.u_cr) ----
    gemm(af, NA, 64, a_w1, a_b1, S->h2, 128, 1, 0, nullptr, nullptr);
    gemm(S->h2, NA, 128, a_w2, a_b2, S->ax, 128, 0, 0, S->u_cr, S->ddA);
    gemm(wf, NW, 128, w_w1, w_b1, S->wtmp, 128, 1, 0, nullptr, nullptr);
    gemm(S->wtmp, NW, 128, w_w2, w_b2, S->wx, 128, 0, 0, S->u_cr, S->ddW);

    // ---- GAT1: creates (artist -> work), ELU; fused s; fused dd2 = wx1.u_in ----
    gemm(S->ax, NA, 128, cr_W, nullptr, S->hsA, 128, 0, 0, cr_as, S->s);
    build_csr(e_cr, e_cr + Ecr, Ecr, NA, NW);
    gat(S->hsA, S->ddW, cr_b, S->wx1, NW, 1, S->u_in, S->dd2);

    // ---- GAT2: infl (work -> work), ELU ----
    gemm(S->wx1, NW, 128, in_W, nullptr, S->hsW, 128, 0, 0, in_as, S->s);
    build_csr(e_in, e_in + Ein, Ein, NW, NW);
    gat(S->hsW, S->dd2, in_b, S->wx2, NW, 1, nullptr, nullptr);

    // ---- GAT3: created_by (work -> artist), no act; fused dd3 = au.u_co ----
    gemm(S->wx2, NW, 128, cr_W, nullptr, S->hsW, 128, 0, 0, cr_as, S->s);
    build_csr(e_cb, e_cb + Ecb, Ecb, NA, NA);
    gat(S->hsW, S->ddA, cr_b, S->au, NA, 0, S->u_co, S->dd3);

    // ---- GAT4: collab (artist -> artist), ELU ----
    gemm(S->au, NA, 128, co_W, nullptr, S->hsA, 128, 0, 0, co_as, S->s);
    build_csr(e_co, e_co + Eco, Eco, NA, NA);
    gat(S->hsA, S->dd3, co_b, S->ac, NA, 1, nullptr, nullptr);

    // ---- predictor ----
    gemm(S->au, NA, 128, p_w1, p_b1, S->h1, 256, 0, 0, nullptr, nullptr);
    gemm(S->ac, NA, 128, p_w1 + 128 * 256, nullptr, S->h1, 256, 1, 1, nullptr, nullptr);
    gemm(S->h1, NA, 256, p_w2, p_b2, S->h2, 128, 1, 0, nullptr, nullptr);
    k_pred<<<ceil_div(NA, 8), 256>>>(S->h2, p_w3, p_b3, out, NA);
}

// round 6
// speedup vs baseline: 1.4265x; 1.2786x over previous
#include <cuda_runtime.h>
#include <cuda_bf16.h>
#include <cstdint>
#include <math.h>

#define NA 20000
#define NW 100000
#define HD 128
#define MAXE 760000

// ===========================================================================
// Scratch
// ===========================================================================
struct Scratch {
    __nv_bfloat16 afhl[NA * 128];            // af  hi|lo (K=64)
    __nv_bfloat16 wfhl[(size_t)NW * 256];    // wf  hi|lo (K=128)
    __nv_bfloat16 hidA[NA * 256];            // artist MLP hidden hi|lo
    __nv_bfloat16 axhl[NA * 256];
    __nv_bfloat16 wx1hl[(size_t)NW * 256];
    __nv_bfloat16 wx2hl[(size_t)NW * 256];
    __nv_bfloat16 auhl[NA * 256];
    __nv_bfloat16 achl[NA * 256];
    __nv_bfloat16 h1hl[NA * 512];            // K=256
    __nv_bfloat16 Bt0[256 * 512];
    __nv_bfloat16 Bt1[256 * 512];
    float hsA[NA * HD];
    float hsW[(size_t)NW * HD];
    float h2f[NA * HD];
    float s[NW];
    float ddW[NW];
    float dd2[NW];
    float ddA[NA];
    float dd3[NA];
    float u_cr[HD];
    float u_in[HD];
    float u_co[HD];
    float v2[HD];
    float c0;
    int cnt[NW];
    int indptr[NW + 1];
    int cursor[NW];
    int csr[MAXE];
    int bsum[1024];
};
__device__ Scratch g_S;

// ===========================================================================
// PTX helpers (portable ISA only: cp.async, ldmatrix, mma.sync — no tcgen05)
// ===========================================================================
__device__ __forceinline__ void cp_async16(uint32_t dst, const void* src) {
    asm volatile("cp.async.cg.shared.global [%0], [%1], 16;\n" :: "r"(dst), "l"(src));
}
__device__ __forceinline__ void cp_commit() { asm volatile("cp.async.commit_group;\n"); }
__device__ __forceinline__ void cp_wait0()  { asm volatile("cp.async.wait_group 0;\n"); }
__device__ __forceinline__ void cp_wait1()  { asm volatile("cp.async.wait_group 1;\n"); }

#define SWZ(off) ((off) ^ (((off) >> 3) & 0x70))

__device__ __forceinline__ void ldmx4(uint32_t& r0, uint32_t& r1, uint32_t& r2,
                                      uint32_t& r3, uint32_t addr) {
    asm volatile("ldmatrix.sync.aligned.m8n8.x4.shared.b16 {%0,%1,%2,%3}, [%4];"
                 : "=r"(r0), "=r"(r1), "=r"(r2), "=r"(r3) : "r"(addr));
}

__device__ __forceinline__ void mma16816(float* d, uint32_t a0, uint32_t a1,
                                         uint32_t a2, uint32_t a3,
                                         uint32_t b0, uint32_t b1) {
    asm volatile(
        "mma.sync.aligned.m16n8k16.row.col.f32.bf16.bf16.f32 "
        "{%0,%1,%2,%3}, {%4,%5,%6,%7}, {%8,%9}, {%0,%1,%2,%3};"
        : "+f"(d[0]), "+f"(d[1]), "+f"(d[2]), "+f"(d[3])
        : "r"(a0), "r"(a1), "r"(a2), "r"(a3), "r"(b0), "r"(b1));
}

// ===========================================================================
// HMMA GEMM.  A (+A2) bf16 hi|lo [M, 2K].  Bt (+Bt2) bf16 hi|lo [n, 2K]
// (K-major = B^T).  C = act(A@B + A2@B2 + bias), split-precision (3 terms).
// Outputs: Cf fp32 and/or Chl bf16 hi|lo [M, 2n]; fused row-dot
// sout[r] = dot(C_row, sv) + (*svc)  (requires gridDim.y == 1).
// BM=128 (8 warps x 16 rows), BN=128, BK=64, double-buffered cp.async.
// ===========================================================================
__global__ __launch_bounds__(256)
void k_tgemm(const __nv_bfloat16* __restrict__ A, const __nv_bfloat16* __restrict__ A2,
             const __nv_bfloat16* __restrict__ Bt, const __nv_bfloat16* __restrict__ Bt2,
             const float* __restrict__ bias,
             float* __restrict__ Cf, __nv_bfloat16* __restrict__ Chl,
             const float* __restrict__ sv, const float* __restrict__ svc,
             float* __restrict__ sout,
             int M, int K, int n, int act)
{
    extern __shared__ char sh[];
    const uint32_t sb = (uint32_t)__cvta_generic_to_shared(sh);
    const uint32_t A_OFF = 0, B_OFF = 32768;

    const int tid = threadIdx.x, wid = tid >> 5, lane = tid & 31;
    const int row0 = blockIdx.x * 128, col0 = blockIdx.y * 128;

    const int KB = K >> 6;
    const int Thalf = 3 * KB;
    const int T = A2 ? 2 * Thalf : Thalf;
    const size_t rs = (size_t)2 * K;

    float d[16][4];
#pragma unroll
    for (int i = 0; i < 16; i++)
#pragma unroll
        for (int j = 0; j < 4; j++) d[i][j] = 0.f;

    auto issue = [&](int t) {
        int b = t & 1;
        int tt = t;
        const __nv_bfloat16 *Ab = A, *Bb = Bt;
        if (A2 && tt >= Thalf) { tt -= Thalf; Ab = A2; Bb = Bt2; }
        const int phase = tt / KB;
        const int kb = tt - phase * KB;
        const int aoff = ((phase == 1) ? K : 0) + kb * 64;
        const int boff = ((phase == 2) ? K : 0) + kb * 64;
#pragma unroll
        for (int i = 0; i < 4; i++) {
            int idx = tid + i * 256;
            int r = idx >> 3, u = idx & 7;
            uint32_t sw = SWZ((uint32_t)(r * 128 + u * 16));
            cp_async16(sb + B_OFF + b * 16384 + sw,
                       Bb + (size_t)(col0 + r) * rs + boff + u * 8);
            int gr = row0 + r;
            if (gr < M)
                cp_async16(sb + A_OFF + b * 16384 + sw,
                           Ab + (size_t)gr * rs + aoff + u * 8);
            else
                *(uint4*)(sh + A_OFF + b * 16384 + sw) = make_uint4(0, 0, 0, 0);
        }
        cp_commit();
    };

    const int g = lane >> 3, lr = lane & 7;
    const int m0 = wid * 16;

    issue(0);
    for (int t = 0; t < T; t++) {
        if (t + 1 < T) { issue(t + 1); cp_wait1(); } else { cp_wait0(); }
        __syncthreads();

        const uint32_t sA = sb + A_OFF + (t & 1) * 16384;
        const uint32_t sB = sb + B_OFF + (t & 1) * 16384;
        const int arow = m0 + lr + ((g & 1) << 3);
        const int brow_lo = (g >> 1) * 8 + lr;
#pragma unroll
        for (int ks = 0; ks < 4; ks++) {
            uint32_t a0, a1, a2, a3;
            int akblk = ks * 2 + (g >> 1);
            ldmx4(a0, a1, a2, a3, sA + SWZ((uint32_t)(arow * 128 + akblk * 16)));
            int bkblk = ks * 2 + (g & 1);
#pragma unroll
            for (int jp = 0; jp < 8; jp++) {
                uint32_t b0, b1, b2, b3;
                int nrow = jp * 16 + brow_lo;
                ldmx4(b0, b1, b2, b3, sB + SWZ((uint32_t)(nrow * 128 + bkblk * 16)));
                mma16816(d[jp * 2], a0, a1, a2, a3, b0, b1);
                mma16816(d[jp * 2 + 1], a0, a1, a2, a3, b2, b3);
            }
        }
        __syncthreads();
    }

    // ---- epilogue ----
    const int r0 = row0 + m0 + (lane >> 2);
    const int r1 = r0 + 8;
    float p0 = 0.f, p1 = 0.f;
#pragma unroll
    for (int nf = 0; nf < 16; nf++) {
        int gc = col0 + nf * 8 + (lane & 3) * 2;
        float v00 = d[nf][0], v01 = d[nf][1], v10 = d[nf][2], v11 = d[nf][3];
        if (bias) {
            float b0 = __ldg(bias + gc), b1 = __ldg(bias + gc + 1);
            v00 += b0; v01 += b1; v10 += b0; v11 += b1;
        }
        if (act == 1) {
            v00 = fmaxf(v00, 0.f); v01 = fmaxf(v01, 0.f);
            v10 = fmaxf(v10, 0.f); v11 = fmaxf(v11, 0.f);
        }
        if (sv) {
            float s0 = __ldg(sv + gc), s1 = __ldg(sv + gc + 1);
            p0 = fmaf(v00, s0, fmaf(v01, s1, p0));
            p1 = fmaf(v10, s0, fmaf(v11, s1, p1));
        }
        if (Cf) {
            if (r0 < M) *(float2*)(Cf + (size_t)r0 * n + gc) = make_float2(v00, v01);
            if (r1 < M) *(float2*)(Cf + (size_t)r1 * n + gc) = make_float2(v10, v11);
        }
        if (Chl) {
            if (r0 < M) {
                __nv_bfloat16 h0 = __float2bfloat16(v00), h1 = __float2bfloat16(v01);
                __nv_bfloat162 hp = __halves2bfloat162(h0, h1);
                __nv_bfloat162 lp = __halves2bfloat162(
                    __float2bfloat16(v00 - __bfloat162float(h0)),
                    __float2bfloat16(v01 - __bfloat162float(h1)));
                *(__nv_bfloat162*)(Chl + (size_t)r0 * 2 * n + gc) = hp;
                *(__nv_bfloat162*)(Chl + (size_t)r0 * 2 * n + n + gc) = lp;
            }
            if (r1 < M) {
                __nv_bfloat16 h0 = __float2bfloat16(v10), h1 = __float2bfloat16(v11);
                __nv_bfloat162 hp = __halves2bfloat162(h0, h1);
                __nv_bfloat162 lp = __halves2bfloat162(
                    __float2bfloat16(v10 - __bfloat162float(h0)),
                    __float2bfloat16(v11 - __bfloat162float(h1)));
                *(__nv_bfloat162*)(Chl + (size_t)r1 * 2 * n + gc) = hp;
                *(__nv_bfloat162*)(Chl + (size_t)r1 * 2 * n + n + gc) = lp;
            }
        }
    }
    if (sv) {
        p0 += __shfl_xor_sync(0xffffffffu, p0, 1);
        p0 += __shfl_xor_sync(0xffffffffu, p0, 2);
        p1 += __shfl_xor_sync(0xffffffffu, p1, 1);
        p1 += __shfl_xor_sync(0xffffffffu, p1, 2);
        if ((lane & 3) == 0) {
            float c = svc ? *svc : 0.f;
            if (r0 < M) sout[r0] = p0 + c;
            if (r1 < M) sout[r1] = p1 + c;
        }
    }
}

// ===========================================================================
// Conversions
// ===========================================================================
__global__ void k_cvtB(const float* __restrict__ B, __nv_bfloat16* __restrict__ Bt,
                       int K, int n)
{
    int i = blockIdx.x * blockDim.x + threadIdx.x;
    if (i >= K * n) return;
    int k = i / n, c = i % n;
    float x = B[i];
    __nv_bfloat16 h = __float2bfloat16(x);
    __nv_bfloat16 l = __float2bfloat16(x - __bfloat162float(h));
    Bt[(size_t)c * 2 * K + k] = h;
    Bt[(size_t)c * 2 * K + K + k] = l;
}

__global__ void k_cvtA(const float* __restrict__ X, __nv_bfloat16* __restrict__ Y,
                       int M, int K)
{
    long i = (long)blockIdx.x * blockDim.x + threadIdx.x;
    if (i >= (long)M * K) return;
    int k = (int)(i % K);
    long m = i / K;
    float x = X[i];
    __nv_bfloat16 h = __float2bfloat16(x);
    __nv_bfloat16 l = __float2bfloat16(x - __bfloat162float(h));
    Y[m * 2 * K + k] = h;
    Y[m * 2 * K + K + k] = l;
}

// ===========================================================================
// small vector kernels
// ===========================================================================
__global__ void k_matvec(const float* __restrict__ W, const float* __restrict__ v,
                         float* __restrict__ u)
{
    int k = threadIdx.x;
    float sm = 0.f;
#pragma unroll 8
    for (int c = 0; c < HD; c++) sm = fmaf(W[k * HD + c], v[c], sm);
    u[k] = sm;
}

__global__ void k_vdot(const float* __restrict__ a, const float* __restrict__ b,
                       float* __restrict__ out)
{
    __shared__ float red[4];
    int t = threadIdx.x;
    float v = a[t] * b[t];
#pragma unroll
    for (int off = 16; off; off >>= 1) v += __shfl_xor_sync(0xffffffffu, v, off);
    if ((t & 31) == 0) red[t >> 5] = v;
    __syncthreads();
    if (t == 0) out[0] = red[0] + red[1] + red[2] + red[3];
}

// ===========================================================================
// CSR build
// ===========================================================================
__global__ void k_zero(int* p, int nv)
{
    int i = blockIdx.x * blockDim.x + threadIdx.x;
    if (i < nv) p[i] = 0;
}

__global__ void k_count(const int* __restrict__ dst, int E, int nloop, int* __restrict__ cnt)
{
    int i = blockIdx.x * blockDim.x + threadIdx.x;
    if (i < E) atomicAdd(&cnt[dst[i]], 1);
    else if (i < E + nloop) atomicAdd(&cnt[i - E], 1);
}

__global__ void k_scan_block(const int* __restrict__ in, int* __restrict__ out,
                             int* __restrict__ bsums, int nv)
{
    __shared__ int sh[1024];
    int i = blockIdx.x * 1024 + threadIdx.x;
    int v = (i < nv) ? in[i] : 0;
    sh[threadIdx.x] = v;
    __syncthreads();
    for (int off = 1; off < 1024; off <<= 1) {
        int t = (threadIdx.x >= off) ? sh[threadIdx.x - off] : 0;
        __syncthreads();
        sh[threadIdx.x] += t;
        __syncthreads();
    }
    if (i < nv) out[i] = sh[threadIdx.x] - v;
    if (threadIdx.x == 1023) bsums[blockIdx.x] = sh[1023];
}

__global__ void k_scan_bsums(int* __restrict__ bsums, int nb, int* __restrict__ total_out)
{
    __shared__ int sh[1024];
    int i = threadIdx.x;
    int v = (i < nb) ? bsums[i] : 0;
    sh[i] = v;
    __syncthreads();
    for (int off = 1; off < 1024; off <<= 1) {
        int t = (i >= off) ? sh[i - off] : 0;
        __syncthreads();
        sh[i] += t;
        __syncthreads();
    }
    if (i < nb) bsums[i] = sh[i] - v;
    if (i == nb - 1) *total_out = sh[i];
}

__global__ void k_scan_add(int* __restrict__ indptr, int* __restrict__ cursor,
                           const int* __restrict__ bsums, int nv)
{
    int i = blockIdx.x * blockDim.x + threadIdx.x;
    if (i < nv) {
        int v = indptr[i] + bsums[i >> 10];
        indptr[i] = v;
        cursor[i] = v;
    }
}

__global__ void k_fill(const int* __restrict__ src, const int* __restrict__ dst,
                       int E, int nloop, int* __restrict__ cursor, int* __restrict__ csr)
{
    int i = blockIdx.x * blockDim.x + threadIdx.x;
    if (i < E) {
        int p = atomicAdd(&cursor[dst[i]], 1);
        csr[p] = src[i];
    } else if (i < E + nloop) {
        int j = i - E;
        int p = atomicAdd(&cursor[j], 1);
        csr[p] = j;
    }
}

// ===========================================================================
// GAT aggregation: one warp per dst node; output bf16 hi|lo [ndst, 256];
// optional fused next-layer d-dot dd_out = out_row . unext.
// ===========================================================================
__global__ void k_gat(const int* __restrict__ indptr, const int* __restrict__ csr,
                      const float* __restrict__ hs, const float* __restrict__ s,
                      const float* __restrict__ d, const float* __restrict__ bias,
                      __nv_bfloat16* __restrict__ ohl, int ndst, int act,
                      const float* __restrict__ unext, float* __restrict__ dd_out)
{
    int w = (blockIdx.x * blockDim.x + threadIdx.x) >> 5;
    int lane = threadIdx.x & 31;
    if (w >= ndst) return;

    int beg = indptr[w], end = indptr[w + 1];
    float4 b4 = ((const float4*)bias)[lane];
    float4 o;

    if (end > beg) {
        float dj = d[w];
        float m = -3.0e38f;
        for (int e = beg + lane; e < end; e += 32) {
            float l = s[csr[e]] + dj;
            l = (l > 0.f) ? l : 0.2f * l;
            m = fmaxf(m, l);
        }
#pragma unroll
        for (int off = 16; off; off >>= 1)
            m = fmaxf(m, __shfl_xor_sync(0xffffffffu, m, off));

        float denom = 0.f;
        float4 acc = make_float4(0.f, 0.f, 0.f, 0.f);
        for (int e = beg; e < end; e++) {
            int sn = csr[e];
            float l = s[sn] + dj;
            l = (l > 0.f) ? l : 0.2f * l;
            float wt = __expf(l - m);
            denom += wt;
            float4 hv = ((const float4*)hs)[(size_t)sn * 32 + lane];
            acc.x = fmaf(wt, hv.x, acc.x);
            acc.y = fmaf(wt, hv.y, acc.y);
            acc.z = fmaf(wt, hv.z, acc.z);
            acc.w = fmaf(wt, hv.w, acc.w);
        }
        float inv = 1.0f / denom;
        o.x = fmaf(acc.x, inv, b4.x);
        o.y = fmaf(acc.y, inv, b4.y);
        o.z = fmaf(acc.z, inv, b4.z);
        o.w = fmaf(acc.w, inv, b4.w);
    } else {
        o = b4;
    }

    if (act == 1) {
        o.x = (o.x > 0.f) ? o.x : expm1f(o.x);
        o.y = (o.y > 0.f) ? o.y : expm1f(o.y);
        o.z = (o.z > 0.f) ? o.z : expm1f(o.z);
        o.w = (o.w > 0.f) ? o.w : expm1f(o.w);
    }

    __nv_bfloat16 hx = __float2bfloat16(o.x), hy = __float2bfloat16(o.y);
    __nv_bfloat16 hz = __float2bfloat16(o.z), hw = __float2bfloat16(o.w);
    __nv_bfloat16 lx = __float2bfloat16(o.x - __bfloat162float(hx));
    __nv_bfloat16 ly = __float2bfloat16(o.y - __bfloat162float(hy));
    __nv_bfloat16 lz = __float2bfloat16(o.z - __bfloat162float(hz));
    __nv_bfloat16 lw = __float2bfloat16(o.w - __bfloat162float(hw));
    __nv_bfloat162 h01 = __halves2bfloat162(hx, hy), h23 = __halves2bfloat162(hz, hw);
    __nv_bfloat162 l01 = __halves2bfloat162(lx, ly), l23 = __halves2bfloat162(lz, lw);
    uint2 hv2 = make_uint2(*(uint32_t*)&h01, *(uint32_t*)&h23);
    uint2 lv2 = make_uint2(*(uint32_t*)&l01, *(uint32_t*)&l23);
    ((uint2*)(ohl + (size_t)w * 256))[lane] = hv2;
    ((uint2*)(ohl + (size_t)w * 256 + 128))[lane] = lv2;

    if (dd_out) {
        float4 u4 = ((const float4*)unext)[lane];
        float p = o.x * u4.x + o.y * u4.y + o.z * u4.z + o.w * u4.w;
#pragma unroll
        for (int off = 16; off; off >>= 1) p += __shfl_xor_sync(0xffffffffu, p, off);
        if (lane == 0) dd_out[w] = p;
    }
}

// ===========================================================================
// final: out[i] = dot(h2[i,:], w3) + b3
// ===========================================================================
__global__ void k_pred(const float* __restrict__ h2, const float* __restrict__ w3,
                       const float* __restrict__ b3, float* __restrict__ out, int nrows)
{
    int w = (blockIdx.x * blockDim.x + threadIdx.x) >> 5;
    int lane = threadIdx.x & 31;
    if (w >= nrows) return;
    float4 x = ((const float4*)h2)[(size_t)w * 32 + lane];
    float4 vv = ((const float4*)w3)[lane];
    float sm = x.x * vv.x + x.y * vv.y + x.z * vv.z + x.w * vv.w;
#pragma unroll
    for (int off = 16; off; off >>= 1) sm += __shfl_xor_sync(0xffffffffu, sm, off);
    if (lane == 0) out[w] = sm + b3[0];
}

// ===========================================================================
static inline int ceil_div(int a, int b) { return (a + b - 1) / b; }
static const int TG_SMEM = 65536;

extern "C" void kernel_launch(void* const* d_in, const int* in_sizes, int n_in,
                              void* d_out, int out_size)
{
    Scratch* S;
    cudaGetSymbolAddress((void**)&S, g_S);
    cudaFuncSetAttribute(k_tgemm, cudaFuncAttributeMaxDynamicSharedMemorySize, TG_SMEM);

    const float* af   = (const float*)d_in[0];
    const float* wf   = (const float*)d_in[1];
    const float* a_w1 = (const float*)d_in[2];
    const float* a_b1 = (const float*)d_in[3];
    const float* a_w2 = (const float*)d_in[4];
    const float* a_b2 = (const float*)d_in[5];
    const float* w_w1 = (const float*)d_in[6];
    const float* w_b1 = (const float*)d_in[7];
    const float* w_w2 = (const float*)d_in[8];
    const float* w_b2 = (const float*)d_in[9];
    const float* cr_W = (const float*)d_in[10];
    const float* cr_b = (const float*)d_in[11];
    const float* cr_as = (const float*)d_in[12];
    const float* cr_ad = (const float*)d_in[13];
    const float* in_W = (const float*)d_in[14];
    const float* in_b = (const float*)d_in[15];
    const float* in_as = (const float*)d_in[16];
    const float* in_ad = (const float*)d_in[17];
    const float* co_W = (const float*)d_in[18];
    const float* co_b = (const float*)d_in[19];
    const float* co_as = (const float*)d_in[20];
    const float* co_ad = (const float*)d_in[21];
    const float* p_w1 = (const float*)d_in[22];
    const float* p_b1 = (const float*)d_in[23];
    const float* p_w2 = (const float*)d_in[24];
    const float* p_b2 = (const float*)d_in[25];
    const float* p_w3 = (const float*)d_in[26];
    const float* p_b3 = (const float*)d_in[27];
    const int* e_cr = (const int*)d_in[28]; int Ecr = in_sizes[28] / 2;
    const int* e_cb = (const int*)d_in[29]; int Ecb = in_sizes[29] / 2;
    const int* e_in = (const int*)d_in[30]; int Ein = in_sizes[30] / 2;
    const int* e_co = (const int*)d_in[31]; int Eco = in_sizes[31] / 2;
    float* out = (float*)d_out;

    auto tg = [&](const __nv_bfloat16* A, const __nv_bfloat16* A2,
                  const __nv_bfloat16* Bt, const __nv_bfloat16* Bt2,
                  const float* bias, float* Cf, __nv_bfloat16* Chl,
                  const float* sv, const float* svc, float* sout,
                  int M, int K, int n, int act) {
        dim3 g(ceil_div(M, 128), n / 128);
        k_tgemm<<<g, 256, TG_SMEM>>>(A, A2, Bt, Bt2, bias, Cf, Chl, sv, svc, sout,
                                     M, K, n, act);
    };
    auto cvtB = [&](const float* B, __nv_bfloat16* Bt, int K, int n) {
        k_cvtB<<<ceil_div(K * n, 256), 256>>>(B, Bt, K, n);
    };
    auto build_csr = [&](const int* src, const int* dst, int E, int nloop, int ndst) {
        k_zero<<<ceil_div(ndst, 256), 256>>>(S->cnt, ndst);
        k_count<<<ceil_div(E + nloop, 256), 256>>>(dst, E, nloop, S->cnt);
        int nb = ceil_div(ndst, 1024);
        k_scan_block<<<nb, 1024>>>(S->cnt, S->indptr, S->bsum, ndst);
        k_scan_bsums<<<1, 1024>>>(S->bsum, nb, S->indptr + ndst);
        k_scan_add<<<ceil_div(ndst, 256), 256>>>(S->indptr, S->cursor, S->bsum, ndst);
        k_fill<<<ceil_div(E + nloop, 256), 256>>>(src, dst, E, nloop, S->cursor, S->csr);
    };
    auto gat = [&](const float* hs, const float* d, const float* bias,
                   __nv_bfloat16* ohl, int ndst, int act,
                   const float* unext, float* dd_out) {
        k_gat<<<ceil_div(ndst, 8), 256>>>(S->indptr, S->csr, hs, S->s, d,
                                          bias, ohl, ndst, act, unext, dd_out);
    };

    // u vectors + folded work-MLP projection
    k_matvec<<<1, 128>>>(cr_W, cr_ad, S->u_cr);
    k_matvec<<<1, 128>>>(in_W, in_ad, S->u_in);
    k_matvec<<<1, 128>>>(co_W, co_ad, S->u_co);
    k_matvec<<<1, 128>>>(w_w2, S->u_cr, S->v2);     // v2 = w_w2 @ u_cr
    k_vdot<<<1, 128>>>(w_b2, S->u_cr, &S->c0);      // c0 = b2 . u_cr

    // feature conversions
    k_cvtA<<<ceil_div(NA * 64, 256), 256>>>(af, S->afhl, NA, 64);
    k_cvtA<<<ceil_div(NW * 128, 256), 256>>>(wf, S->wfhl, NW, 128);

    // persistent cr_W operand (GAT1 & GAT3)
    cvtB(cr_W, S->Bt1, 128, 128);

    // ---- artist MLP ----
    cvtB(a_w1, S->Bt0, 64, 128);
    tg(S->afhl, nullptr, S->Bt0, nullptr, a_b1, nullptr, S->hidA,
       nullptr, nullptr, nullptr, NA, 64, 128, 1);
    cvtB(a_w2, S->Bt0, 128, 128);
    tg(S->hidA, nullptr, S->Bt0, nullptr, a_b2, nullptr, S->axhl,
       S->u_cr, nullptr, S->ddA, NA, 128, 128, 0);             // ddA = ax.u_cr

    // ---- work MLP folded: ddW = relu(wf@w_w1+b1).v2 + c0 (no stored output) ----
    cvtB(w_w1, S->Bt0, 128, 128);
    tg(S->wfhl, nullptr, S->Bt0, nullptr, w_b1, nullptr, nullptr,
       S->v2, &S->c0, S->ddW, NW, 128, 128, 1);

    // ---- GAT1: creates (artist -> work), ELU ----
    tg(S->axhl, nullptr, S->Bt1, nullptr, nullptr, S->hsA, nullptr,
       cr_as, nullptr, S->s, NA, 128, 128, 0);                 // hsA, s
    build_csr(e_cr, e_cr + Ecr, Ecr, NA, NW);
    gat(S->hsA, S->ddW, cr_b, S->wx1hl, NW, 1, S->u_in, S->dd2);

    // ---- GAT2: infl (work -> work), ELU ----
    cvtB(in_W, S->Bt0, 128, 128);
    tg(S->wx1hl, nullptr, S->Bt0, nullptr, nullptr, S->hsW, nullptr,
       in_as, nullptr, S->s, NW, 128, 128, 0);
    build_csr(e_in, e_in + Ein, Ein, NW, NW);
    gat(S->hsW, S->dd2, in_b, S->wx2hl, NW, 1, nullptr, nullptr);

    // ---- GAT3: created_by (work -> artist), no act ----
    tg(S->wx2hl, nullptr, S->Bt1, nullptr, nullptr, S->hsW, nullptr,
       cr_as, nullptr, S->s, NW, 128, 128, 0);
    build_csr(e_cb, e_cb + Ecb, Ecb, NA, NA);
    gat(S->hsW, S->ddA, cr_b, S->auhl, NA, 0, S->u_co, S->dd3);

    // ---- GAT4: collab (artist -> artist), ELU ----
    cvtB(co_W, S->Bt0, 128, 128);
    tg(S->auhl, nullptr, S->Bt0, nullptr, nullptr, S->hsA, nullptr,
       co_as, nullptr, S->s, NA, 128, 128, 0);
    build_csr(e_co, e_co + Eco, Eco, NA, NA);
    gat(S->hsA, S->dd3, co_b, S->achl, NA, 1, nullptr, nullptr);

    // ---- predictor ----
    cvtB(p_w1, S->Bt0, 128, 256);
    cvtB(p_w1 + 128 * 256, S->Bt1, 128, 256);
    tg(S->auhl, S->achl, S->Bt0, S->Bt1, p_b1, nullptr, S->h1hl,
       nullptr, nullptr, nullptr, NA, 128, 256, 1);
    cvtB(p_w2, S->Bt0, 256, 128);
    tg(S->h1hl, nullptr, S->Bt0, nullptr, p_b2, S->h2f, nullptr,
       nullptr, nullptr, nullptr, NA, 256, 128, 1);
    k_pred<<<ceil_div(NA, 8), 256>>>(S->h2f, p_w3, p_b3, out, NA);
}

// round 11
// speedup vs baseline: 1.6501x; 1.1568x over previous
#include <cuda_runtime.h>
#include <cuda_bf16.h>
#include <cstdint>
#include <math.h>

#define NA 20000
#define NW 100000
#define HD 128
#define NV_ALL (2 * NW + 2 * NA)     // 240000
#define CSR_ALL 2000000

// ===========================================================================
// Scratch
// ===========================================================================
struct Scratch {
    __nv_bfloat16 afhl[NA * 128];
    __nv_bfloat16 wfhl[(size_t)NW * 256];
    __nv_bfloat16 hidA[NA * 256];
    __nv_bfloat16 axhl[NA * 256];
    __nv_bfloat16 wx1hl[(size_t)NW * 256];
    __nv_bfloat16 wx2hl[(size_t)NW * 256];
    __nv_bfloat16 auhl[NA * 256];
    __nv_bfloat16 achl[NA * 256];
    __nv_bfloat16 h1hl[NA * 512];
    // weight operands (hi|lo, K-major [n][2K])
    __nv_bfloat16 Bt_aw1[128 * 128];
    __nv_bfloat16 Bt_aw2[128 * 256];
    __nv_bfloat16 Bt_ww1[128 * 256];
    __nv_bfloat16 Bt_crW[128 * 256];
    __nv_bfloat16 Bt_inW[128 * 256];
    __nv_bfloat16 Bt_coW[128 * 256];
    __nv_bfloat16 Bt_pw1a[256 * 256];
    __nv_bfloat16 Bt_pw1b[256 * 256];
    __nv_bfloat16 Bt_pw2[128 * 512];
    float hsA[NA * HD];
    float hsW[(size_t)NW * HD];
    float s[NW];
    float ddW[NW];
    float dd2[NW];
    float ddA[NA];
    float dd3[NA];
    float u_cr[HD];
    float u_in[HD];
    float u_co[HD];
    float v2[HD];
    float c0;
    int cnt[NV_ALL];          // also becomes indptr after scan
    int indptr[NV_ALL + 1];
    int cursor[NV_ALL];
    int csr[CSR_ALL];
    int bsum[1024];
};
__device__ Scratch g_S;

// ===========================================================================
// PTX helpers (portable ISA only)
// ===========================================================================
__device__ __forceinline__ void cp_async16(uint32_t dst, const void* src) {
    asm volatile("cp.async.cg.shared.global [%0], [%1], 16;\n" :: "r"(dst), "l"(src));
}
__device__ __forceinline__ void cp_commit() { asm volatile("cp.async.commit_group;\n"); }
__device__ __forceinline__ void cp_wait0()  { asm volatile("cp.async.wait_group 0;\n"); }
__device__ __forceinline__ void cp_wait1()  { asm volatile("cp.async.wait_group 1;\n"); }

#define SWZ(off) ((off) ^ (((off) >> 3) & 0x70))

__device__ __forceinline__ void ldmx4(uint32_t& r0, uint32_t& r1, uint32_t& r2,
                                      uint32_t& r3, uint32_t addr) {
    asm volatile("ldmatrix.sync.aligned.m8n8.x4.shared.b16 {%0,%1,%2,%3}, [%4];"
                 : "=r"(r0), "=r"(r1), "=r"(r2), "=r"(r3) : "r"(addr));
}

__device__ __forceinline__ void mma16816(float* d, uint32_t a0, uint32_t a1,
                                         uint32_t a2, uint32_t a3,
                                         uint32_t b0, uint32_t b1) {
    asm volatile(
        "mma.sync.aligned.m16n8k16.row.col.f32.bf16.bf16.f32 "
        "{%0,%1,%2,%3}, {%4,%5,%6,%7}, {%8,%9}, {%0,%1,%2,%3};"
        : "+f"(d[0]), "+f"(d[1]), "+f"(d[2]), "+f"(d[3])
        : "r"(a0), "r"(a1), "r"(a2), "r"(a3), "r"(b0), "r"(b1));
}

// ===========================================================================
// HMMA GEMM (identical core to R6, proven).
// ===========================================================================
__global__ __launch_bounds__(256)
void k_tgemm(const __nv_bfloat16* __restrict__ A, const __nv_bfloat16* __restrict__ A2,
             const __nv_bfloat16* __restrict__ Bt, const __nv_bfloat16* __restrict__ Bt2,
             const float* __restrict__ bias,
             float* __restrict__ Cf, __nv_bfloat16* __restrict__ Chl,
             const float* __restrict__ sv, const float* __restrict__ svc,
             float* __restrict__ sout,
             int M, int K, int n, int act)
{
    extern __shared__ char sh[];
    const uint32_t sb = (uint32_t)__cvta_generic_to_shared(sh);
    const uint32_t A_OFF = 0, B_OFF = 32768;

    const int tid = threadIdx.x, wid = tid >> 5, lane = tid & 31;
    const int row0 = blockIdx.x * 128, col0 = blockIdx.y * 128;

    const int KB = K >> 6;
    const int Thalf = 3 * KB;
    const int T = A2 ? 2 * Thalf : Thalf;
    const size_t rs = (size_t)2 * K;

    float d[16][4];
#pragma unroll
    for (int i = 0; i < 16; i++)
#pragma unroll
        for (int j = 0; j < 4; j++) d[i][j] = 0.f;

    auto issue = [&](int t) {
        int b = t & 1;
        int tt = t;
        const __nv_bfloat16 *Ab = A, *Bb = Bt;
        if (A2 && tt >= Thalf) { tt -= Thalf; Ab = A2; Bb = Bt2; }
        const int phase = tt / KB;
        const int kb = tt - phase * KB;
        const int aoff = ((phase == 1) ? K : 0) + kb * 64;
        const int boff = ((phase == 2) ? K : 0) + kb * 64;
#pragma unroll
        for (int i = 0; i < 4; i++) {
            int idx = tid + i * 256;
            int r = idx >> 3, u = idx & 7;
            uint32_t sw = SWZ((uint32_t)(r * 128 + u * 16));
            cp_async16(sb + B_OFF + b * 16384 + sw,
                       Bb + (size_t)(col0 + r) * rs + boff + u * 8);
            int gr = row0 + r;
            if (gr < M)
                cp_async16(sb + A_OFF + b * 16384 + sw,
                           Ab + (size_t)gr * rs + aoff + u * 8);
            else
                *(uint4*)(sh + A_OFF + b * 16384 + sw) = make_uint4(0, 0, 0, 0);
        }
        cp_commit();
    };

    const int g = lane >> 3, lr = lane & 7;
    const int m0 = wid * 16;

    issue(0);
    for (int t = 0; t < T; t++) {
        if (t + 1 < T) { issue(t + 1); cp_wait1(); } else { cp_wait0(); }
        __syncthreads();

        const uint32_t sA = sb + A_OFF + (t & 1) * 16384;
        const uint32_t sB = sb + B_OFF + (t & 1) * 16384;
        const int arow = m0 + lr + ((g & 1) << 3);
        const int brow_lo = (g >> 1) * 8 + lr;
#pragma unroll
        for (int ks = 0; ks < 4; ks++) {
            uint32_t a0, a1, a2, a3;
            int akblk = ks * 2 + (g >> 1);
            ldmx4(a0, a1, a2, a3, sA + SWZ((uint32_t)(arow * 128 + akblk * 16)));
            int bkblk = ks * 2 + (g & 1);
#pragma unroll
            for (int jp = 0; jp < 8; jp++) {
                uint32_t b0, b1, b2, b3;
                int nrow = jp * 16 + brow_lo;
                ldmx4(b0, b1, b2, b3, sB + SWZ((uint32_t)(nrow * 128 + bkblk * 16)));
                mma16816(d[jp * 2], a0, a1, a2, a3, b0, b1);
                mma16816(d[jp * 2 + 1], a0, a1, a2, a3, b2, b3);
            }
        }
        __syncthreads();
    }

    const int r0 = row0 + m0 + (lane >> 2);
    const int r1 = r0 + 8;
    float p0 = 0.f, p1 = 0.f;
#pragma unroll
    for (int nf = 0; nf < 16; nf++) {
        int gc = col0 + nf * 8 + (lane & 3) * 2;
        float v00 = d[nf][0], v01 = d[nf][1], v10 = d[nf][2], v11 = d[nf][3];
        if (bias) {
            float b0 = __ldg(bias + gc), b1 = __ldg(bias + gc + 1);
            v00 += b0; v01 += b1; v10 += b0; v11 += b1;
        }
        if (act == 1) {
            v00 = fmaxf(v00, 0.f); v01 = fmaxf(v01, 0.f);
            v10 = fmaxf(v10, 0.f); v11 = fmaxf(v11, 0.f);
        }
        if (sv) {
            float s0 = __ldg(sv + gc), s1 = __ldg(sv + gc + 1);
            p0 = fmaf(v00, s0, fmaf(v01, s1, p0));
            p1 = fmaf(v10, s0, fmaf(v11, s1, p1));
        }
        if (Cf) {
            if (r0 < M) *(float2*)(Cf + (size_t)r0 * n + gc) = make_float2(v00, v01);
            if (r1 < M) *(float2*)(Cf + (size_t)r1 * n + gc) = make_float2(v10, v11);
        }
        if (Chl) {
            if (r0 < M) {
                __nv_bfloat16 h0 = __float2bfloat16(v00), h1 = __float2bfloat16(v01);
                __nv_bfloat162 hp = __halves2bfloat162(h0, h1);
                __nv_bfloat162 lp = __halves2bfloat162(
                    __float2bfloat16(v00 - __bfloat162float(h0)),
                    __float2bfloat16(v01 - __bfloat162float(h1)));
                *(__nv_bfloat162*)(Chl + (size_t)r0 * 2 * n + gc) = hp;
                *(__nv_bfloat162*)(Chl + (size_t)r0 * 2 * n + n + gc) = lp;
            }
            if (r1 < M) {
                __nv_bfloat16 h0 = __float2bfloat16(v10), h1 = __float2bfloat16(v11);
                __nv_bfloat162 hp = __halves2bfloat162(h0, h1);
                __nv_bfloat162 lp = __halves2bfloat162(
                    __float2bfloat16(v10 - __bfloat162float(h0)),
                    __float2bfloat16(v11 - __bfloat162float(h1)));
                *(__nv_bfloat162*)(Chl + (size_t)r1 * 2 * n + gc) = hp;
                *(__nv_bfloat162*)(Chl + (size_t)r1 * 2 * n + n + gc) = lp;
            }
        }
    }
    if (sv) {
        p0 += __shfl_xor_sync(0xffffffffu, p0, 1);
        p0 += __shfl_xor_sync(0xffffffffu, p0, 2);
        p1 += __shfl_xor_sync(0xffffffffu, p1, 1);
        p1 += __shfl_xor_sync(0xffffffffu, p1, 2);
        if ((lane & 3) == 0) {
            float c = svc ? *svc : 0.f;
            if (r0 < M) sout[r0] = p0 + c;
            if (r1 < M) sout[r1] = p1 + c;
        }
    }
}

// ===========================================================================
// Prelude: 3 matvecs in one kernel (warp-per-row, coalesced)
// ===========================================================================
__global__ void k_mv3(const float* __restrict__ W0, const float* __restrict__ v0,
                      float* __restrict__ u0,
                      const float* __restrict__ W1, const float* __restrict__ v1,
                      float* __restrict__ u1,
                      const float* __restrict__ W2, const float* __restrict__ v2,
                      float* __restrict__ u2)
{
    const float* W; const float* v; float* u;
    if (blockIdx.y == 0) { W = W0; v = v0; u = u0; }
    else if (blockIdx.y == 1) { W = W1; v = v1; u = u1; }
    else { W = W2; v = v2; u = u2; }
    int wid = threadIdx.x >> 5, lane = threadIdx.x & 31;
    int row = blockIdx.x * 8 + wid;
    float sm = 0.f;
#pragma unroll
    for (int c = lane; c < 128; c += 32) sm = fmaf(W[row * 128 + c], v[c], sm);
#pragma unroll
    for (int off = 16; off; off >>= 1) sm += __shfl_xor_sync(0xffffffffu, sm, off);
    if (lane == 0) u[row] = sm;
}

// v2 = w_w2 @ u_cr ; c0 = w_b2 . u_cr
__global__ void k_mv2(const float* __restrict__ w_w2, const float* __restrict__ u_cr,
                      float* __restrict__ v2,
                      const float* __restrict__ w_b2, float* __restrict__ c0)
{
    if (blockIdx.x < 16) {
        int wid = threadIdx.x >> 5, lane = threadIdx.x & 31;
        int row = blockIdx.x * 8 + wid;
        float sm = 0.f;
#pragma unroll
        for (int c = lane; c < 128; c += 32) sm = fmaf(w_w2[row * 128 + c], u_cr[c], sm);
#pragma unroll
        for (int off = 16; off; off >>= 1) sm += __shfl_xor_sync(0xffffffffu, sm, off);
        if (lane == 0) v2[row] = sm;
    } else {
        __shared__ float red[4];
        int t = threadIdx.x;
        float v = (t < 128) ? w_b2[t] * u_cr[t] : 0.f;
#pragma unroll
        for (int off = 16; off; off >>= 1) v += __shfl_xor_sync(0xffffffffu, v, off);
        if ((t & 31) == 0) red[t >> 5] = v;
        __syncthreads();
        if (t == 0) c0[0] = red[0] + red[1] + red[2] + red[3];
    }
}

// ===========================================================================
// Conversions
// ===========================================================================
struct CvtJobs {
    const float* src[9];
    __nv_bfloat16* dst[9];
    int K[9], n[9];
};

__global__ void k_cvtW(CvtJobs J)
{
    int g = blockIdx.y;
    int K = J.K[g], n = J.n[g];
    int i = blockIdx.x * 256 + threadIdx.x;
    if (i >= K * n) return;
    int k = i / n, c = i % n;
    float x = J.src[g][i];
    __nv_bfloat16 h = __float2bfloat16(x);
    __nv_bfloat16 l = __float2bfloat16(x - __bfloat162float(h));
    J.dst[g][(size_t)c * 2 * K + k] = h;
    J.dst[g][(size_t)c * 2 * K + K + k] = l;
}

__global__ void k_cvtA(const float* __restrict__ X, __nv_bfloat16* __restrict__ Y,
                       int M, int K)
{
    long i = (long)blockIdx.x * blockDim.x + threadIdx.x;
    if (i >= (long)M * K) return;
    int k = (int)(i % K);
    long m = i / K;
    float x = X[i];
    __nv_bfloat16 h = __float2bfloat16(x);
    __nv_bfloat16 l = __float2bfloat16(x - __bfloat162float(h));
    Y[m * 2 * K + k] = h;
    Y[m * 2 * K + K + k] = l;
}

// ===========================================================================
// Unified CSR build for all 4 graphs
// ===========================================================================
__global__ void k_count_all(const int* __restrict__ d0, int E0, int L0, int o0,
                            const int* __restrict__ d1, int E1, int L1, int o1,
                            const int* __restrict__ d2, int E2, int L2, int o2,
                            const int* __restrict__ d3, int E3, int L3, int o3,
                            int* __restrict__ cnt)
{
    int i = blockIdx.x * 256 + threadIdx.x;
    int T0 = E0 + L0, T1 = E1 + L1, T2 = E2 + L2, T3 = E3 + L3;
    if (i < T0) { atomicAdd(cnt + o0 + ((i < E0) ? d0[i] : i - E0), 1); return; }
    i -= T0;
    if (i < T1) { atomicAdd(cnt + o1 + ((i < E1) ? d1[i] : i - E1), 1); return; }
    i -= T1;
    if (i < T2) { atomicAdd(cnt + o2 + ((i < E2) ? d2[i] : i - E2), 1); return; }
    i -= T2;
    if (i < T3) { atomicAdd(cnt + o3 + ((i < E3) ? d3[i] : i - E3), 1); }
}

__global__ void k_fill_all(const int* __restrict__ s0, const int* __restrict__ d0,
                           int E0, int L0, int o0,
                           const int* __restrict__ s1, const int* __restrict__ d1,
                           int E1, int L1, int o1,
                           const int* __restrict__ s2, const int* __restrict__ d2,
                           int E2, int L2, int o2,
                           const int* __restrict__ s3, const int* __restrict__ d3,
                           int E3, int L3, int o3,
                           int* __restrict__ cursor, int* __restrict__ csr)
{
    int i = blockIdx.x * 256 + threadIdx.x;
    int T0 = E0 + L0, T1 = E1 + L1, T2 = E2 + L2, T3 = E3 + L3;
    const int* sp; const int* dp; int E, off;
    if (i < T0) { sp = s0; dp = d0; E = E0; off = o0; }
    else {
        i -= T0;
        if (i < T1) { sp = s1; dp = d1; E = E1; off = o1; }
        else {
            i -= T1;
            if (i < T2) { sp = s2; dp = d2; E = E2; off = o2; }
            else {
                i -= T2;
                if (i >= T3) return;
                sp = s3; dp = d3; E = E3; off = o3;
            }
        }
    }
    int dst = (i < E) ? dp[i] : i - E;
    int src = (i < E) ? sp[i] : i - E;
    int p = atomicAdd(cursor + off + dst, 1);
    csr[p] = src;
}

__global__ void k_scan_block(const int* __restrict__ in, int* __restrict__ out,
                             int* __restrict__ bsums, int nv)
{
    __shared__ int sh[1024];
    int i = blockIdx.x * 1024 + threadIdx.x;
    int v = (i < nv) ? in[i] : 0;
    sh[threadIdx.x] = v;
    __syncthreads();
    for (int off = 1; off < 1024; off <<= 1) {
        int t = (threadIdx.x >= off) ? sh[threadIdx.x - off] : 0;
        __syncthreads();
        sh[threadIdx.x] += t;
        __syncthreads();
    }
    if (i < nv) out[i] = sh[threadIdx.x] - v;
    if (threadIdx.x == 1023) bsums[blockIdx.x] = sh[1023];
}

__global__ void k_scan_bsums(int* __restrict__ bsums, int nb, int* __restrict__ total_out)
{
    __shared__ int sh[1024];
    int i = threadIdx.x;
    int v = (i < nb) ? bsums[i] : 0;
    sh[i] = v;
    __syncthreads();
    for (int off = 1; off < 1024; off <<= 1) {
        int t = (i >= off) ? sh[i - off] : 0;
        __syncthreads();
        sh[i] += t;
        __syncthreads();
    }
    if (i < nb) bsums[i] = sh[i] - v;
    if (i == nb - 1) *total_out = sh[i];
}

__global__ void k_scan_add(int* __restrict__ indptr, int* __restrict__ cursor,
                           const int* __restrict__ bsums, int nv)
{
    int i = blockIdx.x * blockDim.x + threadIdx.x;
    if (i < nv) {
        int v = indptr[i] + bsums[i >> 10];
        indptr[i] = v;
        cursor[i] = v;
    }
}

// ===========================================================================
// GAT aggregation (one warp / dst), global CSR with per-graph offset.
// ===========================================================================
__global__ void k_gat(const int* __restrict__ indptr, const int* __restrict__ csr,
                      int off,
                      const float* __restrict__ hs, const float* __restrict__ s,
                      const float* __restrict__ d, const float* __restrict__ bias,
                      __nv_bfloat16* __restrict__ ohl, int ndst, int act,
                      const float* __restrict__ unext, float* __restrict__ dd_out)
{
    int w = (blockIdx.x * blockDim.x + threadIdx.x) >> 5;
    int lane = threadIdx.x & 31;
    if (w >= ndst) return;

    int beg = indptr[off + w], end = indptr[off + w + 1];
    float4 b4 = ((const float4*)bias)[lane];
    float4 o;

    if (end > beg) {
        float dj = d[w];
        float m = -3.0e38f;
        for (int e = beg + lane; e < end; e += 32) {
            float l = s[csr[e]] + dj;
            l = (l > 0.f) ? l : 0.2f * l;
            m = fmaxf(m, l);
        }
#pragma unroll
        for (int off2 = 16; off2; off2 >>= 1)
            m = fmaxf(m, __shfl_xor_sync(0xffffffffu, m, off2));

        float denom = 0.f;
        float4 acc = make_float4(0.f, 0.f, 0.f, 0.f);
        for (int e = beg; e < end; e++) {
            int sn = csr[e];
            float l = s[sn] + dj;
            l = (l > 0.f) ? l : 0.2f * l;
            float wt = __expf(l - m);
            denom += wt;
            float4 hv = ((const float4*)hs)[(size_t)sn * 32 + lane];
            acc.x = fmaf(wt, hv.x, acc.x);
            acc.y = fmaf(wt, hv.y, acc.y);
            acc.z = fmaf(wt, hv.z, acc.z);
            acc.w = fmaf(wt, hv.w, acc.w);
        }
        float inv = 1.0f / denom;
        o.x = fmaf(acc.x, inv, b4.x);
        o.y = fmaf(acc.y, inv, b4.y);
        o.z = fmaf(acc.z, inv, b4.z);
        o.w = fmaf(acc.w, inv, b4.w);
    } else {
        o = b4;
    }

    if (act == 1) {
        o.x = (o.x > 0.f) ? o.x : expm1f(o.x);
        o.y = (o.y > 0.f) ? o.y : expm1f(o.y);
        o.z = (o.z > 0.f) ? o.z : expm1f(o.z);
        o.w = (o.w > 0.f) ? o.w : expm1f(o.w);
    }

    __nv_bfloat16 hx = __float2bfloat16(o.x), hy = __float2bfloat16(o.y);
    __nv_bfloat16 hz = __float2bfloat16(o.z), hw = __float2bfloat16(o.w);
    __nv_bfloat16 lx = __float2bfloat16(o.x - __bfloat162float(hx));
    __nv_bfloat16 ly = __float2bfloat16(o.y - __bfloat162float(hy));
    __nv_bfloat16 lz = __float2bfloat16(o.z - __bfloat162float(hz));
    __nv_bfloat16 lw = __float2bfloat16(o.w - __bfloat162float(hw));
    __nv_bfloat162 h01 = __halves2bfloat162(hx, hy), h23 = __halves2bfloat162(hz, hw);
    __nv_bfloat162 l01 = __halves2bfloat162(lx, ly), l23 = __halves2bfloat162(lz, lw);
    uint2 hv2 = make_uint2(*(uint32_t*)&h01, *(uint32_t*)&h23);
    uint2 lv2 = make_uint2(*(uint32_t*)&l01, *(uint32_t*)&l23);
    ((uint2*)(ohl + (size_t)w * 256))[lane] = hv2;
    ((uint2*)(ohl + (size_t)w * 256 + 128))[lane] = lv2;

    if (dd_out) {
        float4 u4 = ((const float4*)unext)[lane];
        float p = o.x * u4.x + o.y * u4.y + o.z * u4.z + o.w * u4.w;
#pragma unroll
        for (int off2 = 16; off2; off2 >>= 1) p += __shfl_xor_sync(0xffffffffu, p, off2);
        if (lane == 0) dd_out[w] = p;
    }
}

// ===========================================================================
static inline int ceil_div(int a, int b) { return (a + b - 1) / b; }
static const int TG_SMEM = 65536;

extern "C" void kernel_launch(void* const* d_in, const int* in_sizes, int n_in,
                              void* d_out, int out_size)
{
    Scratch* S;
    cudaGetSymbolAddress((void**)&S, g_S);
    cudaFuncSetAttribute(k_tgemm, cudaFuncAttributeMaxDynamicSharedMemorySize, TG_SMEM);

    const float* af   = (const float*)d_in[0];
    const float* wf   = (const float*)d_in[1];
    const float* a_w1 = (const float*)d_in[2];
    const float* a_b1 = (const float*)d_in[3];
    const float* a_w2 = (const float*)d_in[4];
    const float* a_b2 = (const float*)d_in[5];
    const float* w_w1 = (const float*)d_in[6];
    const float* w_b1 = (const float*)d_in[7];
    const float* w_w2 = (const float*)d_in[8];
    const float* w_b2 = (const float*)d_in[9];
    const float* cr_W = (const float*)d_in[10];
    const float* cr_b = (const float*)d_in[11];
    const float* cr_as = (const float*)d_in[12];
    const float* cr_ad = (const float*)d_in[13];
    const float* in_W = (const float*)d_in[14];
    const float* in_b = (const float*)d_in[15];
    const float* in_as = (const float*)d_in[16];
    const float* in_ad = (const float*)d_in[17];
    const float* co_W = (const float*)d_in[18];
    const float* co_b = (const float*)d_in[19];
    const float* co_as = (const float*)d_in[20];
    const float* co_ad = (const float*)d_in[21];
    const float* p_w1 = (const float*)d_in[22];
    const float* p_b1 = (const float*)d_in[23];
    const float* p_w2 = (const float*)d_in[24];
    const float* p_b2 = (const float*)d_in[25];
    const float* p_w3 = (const float*)d_in[26];
    const float* p_b3 = (const float*)d_in[27];
    const int* e_cr = (const int*)d_in[28]; int Ecr = in_sizes[28] / 2;
    const int* e_cb = (const int*)d_in[29]; int Ecb = in_sizes[29] / 2;
    const int* e_in = (const int*)d_in[30]; int Ein = in_sizes[30] / 2;
    const int* e_co = (const int*)d_in[31]; int Eco = in_sizes[31] / 2;
    float* out = (float*)d_out;

    // graph segment offsets in the unified node domain
    const int O0 = 0, O1 = NW, O2 = 2 * NW, O3 = 2 * NW + NA;

    auto tg = [&](const __nv_bfloat16* A, const __nv_bfloat16* A2,
                  const __nv_bfloat16* Bt, const __nv_bfloat16* Bt2,
                  const float* bias, float* Cf, __nv_bfloat16* Chl,
                  const float* sv, const float* svc, float* sout,
                  int M, int K, int n, int act) {
        dim3 g(ceil_div(M, 128), n / 128);
        k_tgemm<<<g, 256, TG_SMEM>>>(A, A2, Bt, Bt2, bias, Cf, Chl, sv, svc, sout,
                                     M, K, n, act);
    };
    auto gat = [&](int off, const float* hs, const float* d, const float* bias,
                   __nv_bfloat16* ohl, int ndst, int act,
                   const float* unext, float* dd_out) {
        k_gat<<<ceil_div(ndst, 8), 256>>>(S->indptr, S->csr, off, hs, S->s, d,
                                          bias, ohl, ndst, act, unext, dd_out);
    };

    // ---- prelude: u vectors + folded work-MLP projection ----
    k_mv3<<<dim3(16, 3), 256>>>(cr_W, cr_ad, S->u_cr,
                                in_W, in_ad, S->u_in,
                                co_W, co_ad, S->u_co);
    k_mv2<<<17, 256>>>(w_w2, S->u_cr, S->v2, w_b2, &S->c0);

    // ---- feature + weight conversions ----
    k_cvtA<<<ceil_div(NA * 64, 256), 256>>>(af, S->afhl, NA, 64);
    k_cvtA<<<ceil_div(NW * 128, 256), 256>>>(wf, S->wfhl, NW, 128);
    {
        CvtJobs J;
        J.src[0] = a_w1; J.dst[0] = S->Bt_aw1;  J.K[0] = 64;  J.n[0] = 128;
        J.src[1] = a_w2; J.dst[1] = S->Bt_aw2;  J.K[1] = 128; J.n[1] = 128;
        J.src[2] = w_w1; J.dst[2] = S->Bt_ww1;  J.K[2] = 128; J.n[2] = 128;
        J.src[3] = cr_W; J.dst[3] = S->Bt_crW;  J.K[3] = 128; J.n[3] = 128;
        J.src[4] = in_W; J.dst[4] = S->Bt_inW;  J.K[4] = 128; J.n[4] = 128;
        J.src[5] = co_W; J.dst[5] = S->Bt_coW;  J.K[5] = 128; J.n[5] = 128;
        J.src[6] = p_w1;             J.dst[6] = S->Bt_pw1a; J.K[6] = 128; J.n[6] = 256;
        J.src[7] = p_w1 + 128 * 256; J.dst[7] = S->Bt_pw1b; J.K[7] = 128; J.n[7] = 256;
        J.src[8] = p_w2;             J.dst[8] = S->Bt_pw2;  J.K[8] = 256; J.n[8] = 128;
        k_cvtW<<<dim3(128, 9), 256>>>(J);
    }

    // ---- unified CSR build (all 4 graphs, up-front) ----
    cudaMemsetAsync(S->cnt, 0, NV_ALL * sizeof(int));
    int Ttot = (Ecr + NA) + (Ein + NW) + (Ecb + NA) + (Eco + NA);
    k_count_all<<<ceil_div(Ttot, 256), 256>>>(
        e_cr + Ecr, Ecr, NA, O0,
        e_in + Ein, Ein, NW, O1,
        e_cb + Ecb, Ecb, NA, O2,
        e_co + Eco, Eco, NA, O3, S->cnt);
    int nb = ceil_div(NV_ALL, 1024);
    k_scan_block<<<nb, 1024>>>(S->cnt, S->indptr, S->bsum, NV_ALL);
    k_scan_bsums<<<1, 1024>>>(S->bsum, nb, S->indptr + NV_ALL);
    k_scan_add<<<ceil_div(NV_ALL, 256), 256>>>(S->indptr, S->cursor, S->bsum, NV_ALL);
    k_fill_all<<<ceil_div(Ttot, 256), 256>>>(
        e_cr, e_cr + Ecr, Ecr, NA, O0,
        e_in, e_in + Ein, Ein, NW, O1,
        e_cb, e_cb + Ecb, Ecb, NA, O2,
        e_co, e_co + Eco, Eco, NA, O3,
        S->cursor, S->csr);

    // ---- artist MLP ----
    tg(S->afhl, nullptr, S->Bt_aw1, nullptr, a_b1, nullptr, S->hidA,
       nullptr, nullptr, nullptr, NA, 64, 128, 1);
    tg(S->hidA, nullptr, S->Bt_aw2, nullptr, a_b2, nullptr, S->axhl,
       S->u_cr, nullptr, S->ddA, NA, 128, 128, 0);

    // ---- work MLP folded: ddW only ----
    tg(S->wfhl, nullptr, S->Bt_ww1, nullptr, w_b1, nullptr, nullptr,
       S->v2, &S->c0, S->ddW, NW, 128, 128, 1);

    // ---- GAT1: creates (artist -> work), ELU ----
    tg(S->axhl, nullptr, S->Bt_crW, nullptr, nullptr, S->hsA, nullptr,
       cr_as, nullptr, S->s, NA, 128, 128, 0);
    gat(O0, S->hsA, S->ddW, cr_b, S->wx1hl, NW, 1, S->u_in, S->dd2);

    // ---- GAT2: infl (work -> work), ELU ----
    tg(S->wx1hl, nullptr, S->Bt_inW, nullptr, nullptr, S->hsW, nullptr,
       in_as, nullptr, S->s, NW, 128, 128, 0);
    gat(O1, S->hsW, S->dd2, in_b, S->wx2hl, NW, 1, nullptr, nullptr);

    // ---- GAT3: created_by (work -> artist), no act ----
    tg(S->wx2hl, nullptr, S->Bt_crW, nullptr, nullptr, S->hsW, nullptr,
       cr_as, nullptr, S->s, NW, 128, 128, 0);
    gat(O2, S->hsW, S->ddA, cr_b, S->auhl, NA, 0, S->u_co, S->dd3);

    // ---- GAT4: collab (artist -> artist), ELU ----
    tg(S->auhl, nullptr, S->Bt_coW, nullptr, nullptr, S->hsA, nullptr,
       co_as, nullptr, S->s, NA, 128, 128, 0);
    gat(O3, S->hsA, S->dd3, co_b, S->achl, NA, 1, nullptr, nullptr);

    // ---- predictor ----
    tg(S->auhl, S->achl, S->Bt_pw1a, S->Bt_pw1b, p_b1, nullptr, S->h1hl,
       nullptr, nullptr, nullptr, NA, 128, 256, 1);
    // final two layers fused: out = relu(h1@p_w2+b2) . p_w3 + b3
    tg(S->h1hl, nullptr, S->Bt_pw2, nullptr, p_b2, nullptr, nullptr,
       p_w3, p_b3, out, NA, 256, 128, 1);
}

// round 16
// speedup vs baseline: 1.7710x; 1.0732x over previous
#include <cuda_runtime.h>
#include <cuda_bf16.h>
#include <cstdint>
#include <math.h>

#define NA 20000
#define NW 100000
#define HD 128
#define NV_ALL (2 * NW + 2 * NA)     // 240000
#define CSR_ALL 2000000

// ===========================================================================
// Scratch
// ===========================================================================
struct Scratch {
    __nv_bfloat16 afhl[NA * 128];
    __nv_bfloat16 wfhl[(size_t)NW * 256];
    __nv_bfloat16 hidA[NA * 256];
    __nv_bfloat16 axhl[NA * 256];
    __nv_bfloat16 wx1hl[(size_t)NW * 256];
    __nv_bfloat16 wx2hl[(size_t)NW * 256];
    __nv_bfloat16 auhl[NA * 256];
    __nv_bfloat16 achl[NA * 256];
    __nv_bfloat16 h1hl[NA * 512];
    __nv_bfloat16 Bt_aw1[128 * 128];
    __nv_bfloat16 Bt_aw2[128 * 256];
    __nv_bfloat16 Bt_ww1[128 * 256];
    __nv_bfloat16 Bt_crW[128 * 256];
    __nv_bfloat16 Bt_inW[128 * 256];
    __nv_bfloat16 Bt_coW[128 * 256];
    __nv_bfloat16 Bt_pw1a[256 * 256];
    __nv_bfloat16 Bt_pw1b[256 * 256];
    __nv_bfloat16 Bt_pw2[128 * 512];
    float hsA[NA * HD];
    float hsW[(size_t)NW * HD];
    float s[NW];
    float ddW[NW];
    float dd2[NW];
    float ddA[NA];
    float dd3[NA];
    float u_cr[HD];
    float u_in[HD];
    float u_co[HD];
    float v2[HD];
    float c0;
    int cnt[NV_ALL];
    int indptr[NV_ALL + 1];
    int cursor[NV_ALL];
    int csr[CSR_ALL];
    int bsum[1024];
};
__device__ Scratch g_S;

// ===========================================================================
// PTX helpers (portable ISA only)
// ===========================================================================
__device__ __forceinline__ void cp_async16(uint32_t dst, const void* src) {
    asm volatile("cp.async.cg.shared.global [%0], [%1], 16;\n" :: "r"(dst), "l"(src));
}
__device__ __forceinline__ void cp_commit() { asm volatile("cp.async.commit_group;\n"); }
__device__ __forceinline__ void cp_wait0()  { asm volatile("cp.async.wait_group 0;\n"); }
__device__ __forceinline__ void cp_wait1()  { asm volatile("cp.async.wait_group 1;\n"); }

#define SWZ(off) ((off) ^ (((off) >> 3) & 0x70))

__device__ __forceinline__ void ldmx4(uint32_t& r0, uint32_t& r1, uint32_t& r2,
                                      uint32_t& r3, uint32_t addr) {
    asm volatile("ldmatrix.sync.aligned.m8n8.x4.shared.b16 {%0,%1,%2,%3}, [%4];"
                 : "=r"(r0), "=r"(r1), "=r"(r2), "=r"(r3) : "r"(addr));
}

__device__ __forceinline__ void mma16816(float* d, uint32_t a0, uint32_t a1,
                                         uint32_t a2, uint32_t a3,
                                         uint32_t b0, uint32_t b1) {
    asm volatile(
        "mma.sync.aligned.m16n8k16.row.col.f32.bf16.bf16.f32 "
        "{%0,%1,%2,%3}, {%4,%5,%6,%7}, {%8,%9}, {%0,%1,%2,%3};"
        : "+f"(d[0]), "+f"(d[1]), "+f"(d[2]), "+f"(d[3])
        : "r"(a0), "r"(a1), "r"(a2), "r"(a3), "r"(b0), "r"(b1));
}

// ===========================================================================
// HMMA GEMM (proven core, unchanged)
// ===========================================================================
__global__ __launch_bounds__(256)
void k_tgemm(const __nv_bfloat16* __restrict__ A, const __nv_bfloat16* __restrict__ A2,
             const __nv_bfloat16* __restrict__ Bt, const __nv_bfloat16* __restrict__ Bt2,
             const float* __restrict__ bias,
             float* __restrict__ Cf, __nv_bfloat16* __restrict__ Chl,
             const float* __restrict__ sv, const float* __restrict__ svc,
             float* __restrict__ sout,
             int M, int K, int n, int act)
{
    extern __shared__ char sh[];
    const uint32_t sb = (uint32_t)__cvta_generic_to_shared(sh);
    const uint32_t A_OFF = 0, B_OFF = 32768;

    const int tid = threadIdx.x, wid = tid >> 5, lane = tid & 31;
    const int row0 = blockIdx.x * 128, col0 = blockIdx.y * 128;

    const int KB = K >> 6;
    const int Thalf = 3 * KB;
    const int T = A2 ? 2 * Thalf : Thalf;
    const size_t rs = (size_t)2 * K;

    float d[16][4];
#pragma unroll
    for (int i = 0; i < 16; i++)
#pragma unroll
        for (int j = 0; j < 4; j++) d[i][j] = 0.f;

    auto issue = [&](int t) {
        int b = t & 1;
        int tt = t;
        const __nv_bfloat16 *Ab = A, *Bb = Bt;
        if (A2 && tt >= Thalf) { tt -= Thalf; Ab = A2; Bb = Bt2; }
        const int phase = tt / KB;
        const int kb = tt - phase * KB;
        const int aoff = ((phase == 1) ? K : 0) + kb * 64;
        const int boff = ((phase == 2) ? K : 0) + kb * 64;
#pragma unroll
        for (int i = 0; i < 4; i++) {
            int idx = tid + i * 256;
            int r = idx >> 3, u = idx & 7;
            uint32_t sw = SWZ((uint32_t)(r * 128 + u * 16));
            cp_async16(sb + B_OFF + b * 16384 + sw,
                       Bb + (size_t)(col0 + r) * rs + boff + u * 8);
            int gr = row0 + r;
            if (gr < M)
                cp_async16(sb + A_OFF + b * 16384 + sw,
                           Ab + (size_t)gr * rs + aoff + u * 8);
            else
                *(uint4*)(sh + A_OFF + b * 16384 + sw) = make_uint4(0, 0, 0, 0);
        }
        cp_commit();
    };

    const int g = lane >> 3, lr = lane & 7;
    const int m0 = wid * 16;

    issue(0);
    for (int t = 0; t < T; t++) {
        if (t + 1 < T) { issue(t + 1); cp_wait1(); } else { cp_wait0(); }
        __syncthreads();

        const uint32_t sA = sb + A_OFF + (t & 1) * 16384;
        const uint32_t sB = sb + B_OFF + (t & 1) * 16384;
        const int arow = m0 + lr + ((g & 1) << 3);
        const int brow_lo = (g >> 1) * 8 + lr;
#pragma unroll
        for (int ks = 0; ks < 4; ks++) {
            uint32_t a0, a1, a2, a3;
            int akblk = ks * 2 + (g >> 1);
            ldmx4(a0, a1, a2, a3, sA + SWZ((uint32_t)(arow * 128 + akblk * 16)));
            int bkblk = ks * 2 + (g & 1);
#pragma unroll
            for (int jp = 0; jp < 8; jp++) {
                uint32_t b0, b1, b2, b3;
                int nrow = jp * 16 + brow_lo;
                ldmx4(b0, b1, b2, b3, sB + SWZ((uint32_t)(nrow * 128 + bkblk * 16)));
                mma16816(d[jp * 2], a0, a1, a2, a3, b0, b1);
                mma16816(d[jp * 2 + 1], a0, a1, a2, a3, b2, b3);
            }
        }
        __syncthreads();
    }

    const int r0 = row0 + m0 + (lane >> 2);
    const int r1 = r0 + 8;
    float p0 = 0.f, p1 = 0.f;
#pragma unroll
    for (int nf = 0; nf < 16; nf++) {
        int gc = col0 + nf * 8 + (lane & 3) * 2;
        float v00 = d[nf][0], v01 = d[nf][1], v10 = d[nf][2], v11 = d[nf][3];
        if (bias) {
            float b0 = __ldg(bias + gc), b1 = __ldg(bias + gc + 1);
            v00 += b0; v01 += b1; v10 += b0; v11 += b1;
        }
        if (act == 1) {
            v00 = fmaxf(v00, 0.f); v01 = fmaxf(v01, 0.f);
            v10 = fmaxf(v10, 0.f); v11 = fmaxf(v11, 0.f);
        }
        if (sv) {
            float s0 = __ldg(sv + gc), s1 = __ldg(sv + gc + 1);
            p0 = fmaf(v00, s0, fmaf(v01, s1, p0));
            p1 = fmaf(v10, s0, fmaf(v11, s1, p1));
        }
        if (Cf) {
            if (r0 < M) *(float2*)(Cf + (size_t)r0 * n + gc) = make_float2(v00, v01);
            if (r1 < M) *(float2*)(Cf + (size_t)r1 * n + gc) = make_float2(v10, v11);
        }
        if (Chl) {
            if (r0 < M) {
                __nv_bfloat16 h0 = __float2bfloat16(v00), h1 = __float2bfloat16(v01);
                __nv_bfloat162 hp = __halves2bfloat162(h0, h1);
                __nv_bfloat162 lp = __halves2bfloat162(
                    __float2bfloat16(v00 - __bfloat162float(h0)),
                    __float2bfloat16(v01 - __bfloat162float(h1)));
                *(__nv_bfloat162*)(Chl + (size_t)r0 * 2 * n + gc) = hp;
                *(__nv_bfloat162*)(Chl + (size_t)r0 * 2 * n + n + gc) = lp;
            }
            if (r1 < M) {
                __nv_bfloat16 h0 = __float2bfloat16(v10), h1 = __float2bfloat16(v11);
                __nv_bfloat162 hp = __halves2bfloat162(h0, h1);
                __nv_bfloat162 lp = __halves2bfloat162(
                    __float2bfloat16(v10 - __bfloat162float(h0)),
                    __float2bfloat16(v11 - __bfloat162float(h1)));
                *(__nv_bfloat162*)(Chl + (size_t)r1 * 2 * n + gc) = hp;
                *(__nv_bfloat162*)(Chl + (size_t)r1 * 2 * n + n + gc) = lp;
            }
        }
    }
    if (sv) {
        p0 += __shfl_xor_sync(0xffffffffu, p0, 1);
        p0 += __shfl_xor_sync(0xffffffffu, p0, 2);
        p1 += __shfl_xor_sync(0xffffffffu, p1, 1);
        p1 += __shfl_xor_sync(0xffffffffu, p1, 2);
        if ((lane & 3) == 0) {
            float c = svc ? *svc : 0.f;
            if (r0 < M) sout[r0] = p0 + c;
            if (r1 < M) sout[r1] = p1 + c;
        }
    }
}

// ===========================================================================
// Prelude matvecs
// ===========================================================================
__global__ void k_mv3(const float* __restrict__ W0, const float* __restrict__ v0,
                      float* __restrict__ u0,
                      const float* __restrict__ W1, const float* __restrict__ v1,
                      float* __restrict__ u1,
                      const float* __restrict__ W2, const float* __restrict__ v2,
                      float* __restrict__ u2)
{
    const float* W; const float* v; float* u;
    if (blockIdx.y == 0) { W = W0; v = v0; u = u0; }
    else if (blockIdx.y == 1) { W = W1; v = v1; u = u1; }
    else { W = W2; v = v2; u = u2; }
    int wid = threadIdx.x >> 5, lane = threadIdx.x & 31;
    int row = blockIdx.x * 8 + wid;
    float sm = 0.f;
#pragma unroll
    for (int c = lane; c < 128; c += 32) sm = fmaf(W[row * 128 + c], v[c], sm);
#pragma unroll
    for (int off = 16; off; off >>= 1) sm += __shfl_xor_sync(0xffffffffu, sm, off);
    if (lane == 0) u[row] = sm;
}

__global__ void k_mv2(const float* __restrict__ w_w2, const float* __restrict__ u_cr,
                      float* __restrict__ v2,
                      const float* __restrict__ w_b2, float* __restrict__ c0)
{
    if (blockIdx.x < 16) {
        int wid = threadIdx.x >> 5, lane = threadIdx.x & 31;
        int row = blockIdx.x * 8 + wid;
        float sm = 0.f;
#pragma unroll
        for (int c = lane; c < 128; c += 32) sm = fmaf(w_w2[row * 128 + c], u_cr[c], sm);
#pragma unroll
        for (int off = 16; off; off >>= 1) sm += __shfl_xor_sync(0xffffffffu, sm, off);
        if (lane == 0) v2[row] = sm;
    } else {
        __shared__ float red[4];
        int t = threadIdx.x;
        float v = (t < 128) ? w_b2[t] * u_cr[t] : 0.f;
#pragma unroll
        for (int off = 16; off; off >>= 1) v += __shfl_xor_sync(0xffffffffu, v, off);
        if ((t & 31) == 0) red[t >> 5] = v;
        __syncthreads();
        if (t == 0) c0[0] = red[0] + red[1] + red[2] + red[3];
    }
}

// ===========================================================================
// Conversions (vectorized, division-free)
// ===========================================================================
template<int K>
__global__ void k_cvtA4(const float* __restrict__ X, __nv_bfloat16* __restrict__ Y,
                        int M)
{
    constexpr int KQ = K / 4;
    int i4 = blockIdx.x * 256 + threadIdx.x;
    if (i4 >= M * KQ) return;
    int m = i4 / KQ;            // KQ constexpr pow2 -> shift
    int kq = i4 - m * KQ;
    float4 x = ((const float4*)X)[i4];
    __nv_bfloat16 h0 = __float2bfloat16(x.x), h1 = __float2bfloat16(x.y);
    __nv_bfloat16 h2 = __float2bfloat16(x.z), h3 = __float2bfloat16(x.w);
    __nv_bfloat162 hp0 = __halves2bfloat162(h0, h1);
    __nv_bfloat162 hp1 = __halves2bfloat162(h2, h3);
    __nv_bfloat162 lp0 = __halves2bfloat162(
        __float2bfloat16(x.x - __bfloat162float(h0)),
        __float2bfloat16(x.y - __bfloat162float(h1)));
    __nv_bfloat162 lp1 = __halves2bfloat162(
        __float2bfloat16(x.z - __bfloat162float(h2)),
        __float2bfloat16(x.w - __bfloat162float(h3)));
    uint2 hv = make_uint2(*(uint32_t*)&hp0, *(uint32_t*)&hp1);
    uint2 lv = make_uint2(*(uint32_t*)&lp0, *(uint32_t*)&lp1);
    ((uint2*)(Y + (size_t)m * 2 * K))[kq] = hv;
    ((uint2*)(Y + (size_t)m * 2 * K + K))[kq] = lv;
}

struct CvtJobs {
    const float* src[9];
    __nv_bfloat16* dst[9];
    int K[9], n[9];
};

__global__ void k_cvtW(CvtJobs J)
{
    int g = blockIdx.y;
    int K = J.K[g], n = J.n[g];
    int i = blockIdx.x * 256 + threadIdx.x;
    if (i >= K * n) return;
    int k = i / n, c = i % n;
    float x = J.src[g][i];
    __nv_bfloat16 h = __float2bfloat16(x);
    __nv_bfloat16 l = __float2bfloat16(x - __bfloat162float(h));
    J.dst[g][(size_t)c * 2 * K + k] = h;
    J.dst[g][(size_t)c * 2 * K + K + k] = l;
}

// ===========================================================================
// Unified CSR build
// ===========================================================================
__global__ void k_count_all(const int* __restrict__ d0, int E0, int L0, int o0,
                            const int* __restrict__ d1, int E1, int L1, int o1,
                            const int* __restrict__ d2, int E2, int L2, int o2,
                            const int* __restrict__ d3, int E3, int L3, int o3,
                            int* __restrict__ cnt)
{
    int i = blockIdx.x * 256 + threadIdx.x;
    int T0 = E0 + L0, T1 = E1 + L1, T2 = E2 + L2, T3 = E3 + L3;
    if (i < T0) { atomicAdd(cnt + o0 + ((i < E0) ? d0[i] : i - E0), 1); return; }
    i -= T0;
    if (i < T1) { atomicAdd(cnt + o1 + ((i < E1) ? d1[i] : i - E1), 1); return; }
    i -= T1;
    if (i < T2) { atomicAdd(cnt + o2 + ((i < E2) ? d2[i] : i - E2), 1); return; }
    i -= T2;
    if (i < T3) { atomicAdd(cnt + o3 + ((i < E3) ? d3[i] : i - E3), 1); }
}

__global__ void k_fill_all(const int* __restrict__ s0, const int* __restrict__ d0,
                           int E0, int L0, int o0,
                           const int* __restrict__ s1, const int* __restrict__ d1,
                           int E1, int L1, int o1,
                           const int* __restrict__ s2, const int* __restrict__ d2,
                           int E2, int L2, int o2,
                           const int* __restrict__ s3, const int* __restrict__ d3,
                           int E3, int L3, int o3,
                           int* __restrict__ cursor, int* __restrict__ csr)
{
    int i = blockIdx.x * 256 + threadIdx.x;
    int T0 = E0 + L0, T1 = E1 + L1, T2 = E2 + L2, T3 = E3 + L3;
    const int* sp; const int* dp; int E, off;
    if (i < T0) { sp = s0; dp = d0; E = E0; off = o0; }
    else {
        i -= T0;
        if (i < T1) { sp = s1; dp = d1; E = E1; off = o1; }
        else {
            i -= T1;
            if (i < T2) { sp = s2; dp = d2; E = E2; off = o2; }
            else {
                i -= T2;
                if (i >= T3) return;
                sp = s3; dp = d3; E = E3; off = o3;
            }
        }
    }
    int dst = (i < E) ? dp[i] : i - E;
    int src = (i < E) ? sp[i] : i - E;
    int p = atomicAdd(cursor + off + dst, 1);
    csr[p] = src;
}

__global__ void k_scan_block(const int* __restrict__ in, int* __restrict__ out,
                             int* __restrict__ bsums, int nv)
{
    __shared__ int sh[1024];
    int i = blockIdx.x * 1024 + threadIdx.x;
    int v = (i < nv) ? in[i] : 0;
    sh[threadIdx.x] = v;
    __syncthreads();
    for (int off = 1; off < 1024; off <<= 1) {
        int t = (threadIdx.x >= off) ? sh[threadIdx.x - off] : 0;
        __syncthreads();
        sh[threadIdx.x] += t;
        __syncthreads();
    }
    if (i < nv) out[i] = sh[threadIdx.x] - v;
    if (threadIdx.x == 1023) bsums[blockIdx.x] = sh[1023];
}

__global__ void k_scan_bsums(int* __restrict__ bsums, int nb, int* __restrict__ total_out)
{
    __shared__ int sh[1024];
    int i = threadIdx.x;
    int v = (i < nb) ? bsums[i] : 0;
    sh[i] = v;
    __syncthreads();
    for (int off = 1; off < 1024; off <<= 1) {
        int t = (i >= off) ? sh[i - off] : 0;
        __syncthreads();
        sh[i] += t;
        __syncthreads();
    }
    if (i < nb) bsums[i] = sh[i] - v;
    if (i == nb - 1) *total_out = sh[i];
}

__global__ void k_scan_add(int* __restrict__ indptr, int* __restrict__ cursor,
                           const int* __restrict__ bsums, int nv)
{
    int i = blockIdx.x * blockDim.x + threadIdx.x;
    if (i < nv) {
        int v = indptr[i] + bsums[i >> 10];
        indptr[i] = v;
        cursor[i] = v;
    }
}

// ===========================================================================
// GAT aggregation: warp/dst.  Fast path deg<=32: edge data held in registers,
// gather loop gets (src, weight) via shuffle -> no dependent-load chain.
// ===========================================================================
__global__ void k_gat(const int* __restrict__ indptr, const int* __restrict__ csr,
                      int off,
                      const float* __restrict__ hs, const float* __restrict__ s,
                      const float* __restrict__ d, const float* __restrict__ bias,
                      __nv_bfloat16* __restrict__ ohl, int ndst, int act,
                      const float* __restrict__ unext, float* __restrict__ dd_out)
{
    int w = (blockIdx.x * blockDim.x + threadIdx.x) >> 5;
    int lane = threadIdx.x & 31;
    if (w >= ndst) return;

    int beg = indptr[off + w], end = indptr[off + w + 1];
    int deg = end - beg;
    float4 b4 = ((const float4*)bias)[lane];
    float4 o;

    if (deg == 0) {
        o = b4;
    } else if (deg <= 32) {
        float dj = d[w];
        int sn = 0;
        float l = -3.0e38f;
        if (lane < deg) {
            sn = csr[beg + lane];
            float t = s[sn] + dj;
            l = (t > 0.f) ? t : 0.2f * t;
        }
        float m = l;
#pragma unroll
        for (int o2 = 16; o2; o2 >>= 1)
            m = fmaxf(m, __shfl_xor_sync(0xffffffffu, m, o2));
        float wt = (lane < deg) ? __expf(l - m) : 0.f;
        float denom = wt;
#pragma unroll
        for (int o2 = 16; o2; o2 >>= 1)
            denom += __shfl_xor_sync(0xffffffffu, denom, o2);
        float4 acc = make_float4(0.f, 0.f, 0.f, 0.f);
        for (int j = 0; j < deg; j++) {
            int snj = __shfl_sync(0xffffffffu, sn, j);
            float wtj = __shfl_sync(0xffffffffu, wt, j);
            float4 hv = ((const float4*)hs)[(size_t)snj * 32 + lane];
            acc.x = fmaf(wtj, hv.x, acc.x);
            acc.y = fmaf(wtj, hv.y, acc.y);
            acc.z = fmaf(wtj, hv.z, acc.z);
            acc.w = fmaf(wtj, hv.w, acc.w);
        }
        float inv = 1.0f / denom;
        o.x = fmaf(acc.x, inv, b4.x);
        o.y = fmaf(acc.y, inv, b4.y);
        o.z = fmaf(acc.z, inv, b4.z);
        o.w = fmaf(acc.w, inv, b4.w);
    } else {
        float dj = d[w];
        float m = -3.0e38f;
        for (int e = beg + lane; e < end; e += 32) {
            float l = s[csr[e]] + dj;
            l = (l > 0.f) ? l : 0.2f * l;
            m = fmaxf(m, l);
        }
#pragma unroll
        for (int o2 = 16; o2; o2 >>= 1)
            m = fmaxf(m, __shfl_xor_sync(0xffffffffu, m, o2));

        float denom = 0.f;
        float4 acc = make_float4(0.f, 0.f, 0.f, 0.f);
        for (int e = beg; e < end; e++) {
            int sn = csr[e];
            float l = s[sn] + dj;
            l = (l > 0.f) ? l : 0.2f * l;
            float wt = __expf(l - m);
            denom += wt;
            float4 hv = ((const float4*)hs)[(size_t)sn * 32 + lane];
            acc.x = fmaf(wt, hv.x, acc.x);
            acc.y = fmaf(wt, hv.y, acc.y);
            acc.z = fmaf(wt, hv.z, acc.z);
            acc.w = fmaf(wt, hv.w, acc.w);
        }
        float inv = 1.0f / denom;
        o.x = fmaf(acc.x, inv, b4.x);
        o.y = fmaf(acc.y, inv, b4.y);
        o.z = fmaf(acc.z, inv, b4.z);
        o.w = fmaf(acc.w, inv, b4.w);
    }

    if (act == 1) {
        o.x = (o.x > 0.f) ? o.x : expm1f(o.x);
        o.y = (o.y > 0.f) ? o.y : expm1f(o.y);
        o.z = (o.z > 0.f) ? o.z : expm1f(o.z);
        o.w = (o.w > 0.f) ? o.w : expm1f(o.w);
    }

    __nv_bfloat16 hx = __float2bfloat16(o.x), hy = __float2bfloat16(o.y);
    __nv_bfloat16 hz = __float2bfloat16(o.z), hw = __float2bfloat16(o.w);
    __nv_bfloat16 lx = __float2bfloat16(o.x - __bfloat162float(hx));
    __nv_bfloat16 ly = __float2bfloat16(o.y - __bfloat162float(hy));
    __nv_bfloat16 lz = __float2bfloat16(o.z - __bfloat162float(hz));
    __nv_bfloat16 lw = __float2bfloat16(o.w - __bfloat162float(hw));
    __nv_bfloat162 h01 = __halves2bfloat162(hx, hy), h23 = __halves2bfloat162(hz, hw);
    __nv_bfloat162 l01 = __halves2bfloat162(lx, ly), l23 = __halves2bfloat162(lz, lw);
    uint2 hv2 = make_uint2(*(uint32_t*)&h01, *(uint32_t*)&h23);
    uint2 lv2 = make_uint2(*(uint32_t*)&l01, *(uint32_t*)&l23);
    ((uint2*)(ohl + (size_t)w * 256))[lane] = hv2;
    ((uint2*)(ohl + (size_t)w * 256 + 128))[lane] = lv2;

    if (dd_out) {
        float4 u4 = ((const float4*)unext)[lane];
        float p = o.x * u4.x + o.y * u4.y + o.z * u4.z + o.w * u4.w;
#pragma unroll
        for (int o2 = 16; o2; o2 >>= 1) p += __shfl_xor_sync(0xffffffffu, p, o2);
        if (lane == 0) dd_out[w] = p;
    }
}

// ===========================================================================
static inline int ceil_div(int a, int b) { return (a + b - 1) / b; }
static const int TG_SMEM = 65536;

extern "C" void kernel_launch(void* const* d_in, const int* in_sizes, int n_in,
                              void* d_out, int out_size)
{
    Scratch* S;
    cudaGetSymbolAddress((void**)&S, g_S);
    cudaFuncSetAttribute(k_tgemm, cudaFuncAttributeMaxDynamicSharedMemorySize, TG_SMEM);

    const float* af   = (const float*)d_in[0];
    const float* wf   = (const float*)d_in[1];
    const float* a_w1 = (const float*)d_in[2];
    const float* a_b1 = (const float*)d_in[3];
    const float* a_w2 = (const float*)d_in[4];
    const float* a_b2 = (const float*)d_in[5];
    const float* w_w1 = (const float*)d_in[6];
    const float* w_b1 = (const float*)d_in[7];
    const float* w_w2 = (const float*)d_in[8];
    const float* w_b2 = (const float*)d_in[9];
    const float* cr_W = (const float*)d_in[10];
    const float* cr_b = (const float*)d_in[11];
    const float* cr_as = (const float*)d_in[12];
    const float* cr_ad = (const float*)d_in[13];
    const float* in_W = (const float*)d_in[14];
    const float* in_b = (const float*)d_in[15];
    const float* in_as = (const float*)d_in[16];
    const float* in_ad = (const float*)d_in[17];
    const float* co_W = (const float*)d_in[18];
    const float* co_b = (const float*)d_in[19];
    const float* co_as = (const float*)d_in[20];
    const float* co_ad = (const float*)d_in[21];
    const float* p_w1 = (const float*)d_in[22];
    const float* p_b1 = (const float*)d_in[23];
    const float* p_w2 = (const float*)d_in[24];
    const float* p_b2 = (const float*)d_in[25];
    const float* p_w3 = (const float*)d_in[26];
    const float* p_b3 = (const float*)d_in[27];
    const int* e_cr = (const int*)d_in[28]; int Ecr = in_sizes[28] / 2;
    const int* e_cb = (const int*)d_in[29]; int Ecb = in_sizes[29] / 2;
    const int* e_in = (const int*)d_in[30]; int Ein = in_sizes[30] / 2;
    const int* e_co = (const int*)d_in[31]; int Eco = in_sizes[31] / 2;
    float* out = (float*)d_out;

    const int O0 = 0, O1 = NW, O2 = 2 * NW, O3 = 2 * NW + NA;

    auto tg = [&](const __nv_bfloat16* A, const __nv_bfloat16* A2,
                  const __nv_bfloat16* Bt, const __nv_bfloat16* Bt2,
                  const float* bias, float* Cf, __nv_bfloat16* Chl,
                  const float* sv, const float* svc, float* sout,
                  int M, int K, int n, int act) {
        dim3 g(ceil_div(M, 128), n / 128);
        k_tgemm<<<g, 256, TG_SMEM>>>(A, A2, Bt, Bt2, bias, Cf, Chl, sv, svc, sout,
                                     M, K, n, act);
    };
    auto gat = [&](int off, const float* hs, const float* d, const float* bias,
                   __nv_bfloat16* ohl, int ndst, int act,
                   const float* unext, float* dd_out) {
        k_gat<<<ceil_div(ndst, 8), 256>>>(S->indptr, S->csr, off, hs, S->s, d,
                                          bias, ohl, ndst, act, unext, dd_out);
    };

    // ---- prelude: u vectors + folded work-MLP projection ----
    k_mv3<<<dim3(16, 3), 256>>>(cr_W, cr_ad, S->u_cr,
                                in_W, in_ad, S->u_in,
                                co_W, co_ad, S->u_co);
    k_mv2<<<17, 256>>>(w_w2, S->u_cr, S->v2, w_b2, &S->c0);

    // ---- feature + weight conversions (vectorized) ----
    k_cvtA4<64><<<ceil_div(NA * 16, 256), 256>>>(af, S->afhl, NA);
    k_cvtA4<128><<<ceil_div(NW * 32, 256), 256>>>(wf, S->wfhl, NW);
    {
        CvtJobs J;
        J.src[0] = a_w1; J.dst[0] = S->Bt_aw1;  J.K[0] = 64;  J.n[0] = 128;
        J.src[1] = a_w2; J.dst[1] = S->Bt_aw2;  J.K[1] = 128; J.n[1] = 128;
        J.src[2] = w_w1; J.dst[2] = S->Bt_ww1;  J.K[2] = 128; J.n[2] = 128;
        J.src[3] = cr_W; J.dst[3] = S->Bt_crW;  J.K[3] = 128; J.n[3] = 128;
        J.src[4] = in_W; J.dst[4] = S->Bt_inW;  J.K[4] = 128; J.n[4] = 128;
        J.src[5] = co_W; J.dst[5] = S->Bt_coW;  J.K[5] = 128; J.n[5] = 128;
        J.src[6] = p_w1;             J.dst[6] = S->Bt_pw1a; J.K[6] = 128; J.n[6] = 256;
        J.src[7] = p_w1 + 128 * 256; J.dst[7] = S->Bt_pw1b; J.K[7] = 128; J.n[7] = 256;
        J.src[8] = p_w2;             J.dst[8] = S->Bt_pw2;  J.K[8] = 256; J.n[8] = 128;
        k_cvtW<<<dim3(128, 9), 256>>>(J);
    }

    // ---- unified CSR build ----
    cudaMemsetAsync(S->cnt, 0, NV_ALL * sizeof(int));
    int Ttot = (Ecr + NA) + (Ein + NW) + (Ecb + NA) + (Eco + NA);
    k_count_all<<<ceil_div(Ttot, 256), 256>>>(
        e_cr + Ecr, Ecr, NA, O0,
        e_in + Ein, Ein, NW, O1,
        e_cb + Ecb, Ecb, NA, O2,
        e_co + Eco, Eco, NA, O3, S->cnt);
    int nb = ceil_div(NV_ALL, 1024);
    k_scan_block<<<nb, 1024>>>(S->cnt, S->indptr, S->bsum, NV_ALL);
    k_scan_bsums<<<1, 1024>>>(S->bsum, nb, S->indptr + NV_ALL);
    k_scan_add<<<ceil_div(NV_ALL, 256), 256>>>(S->indptr, S->cursor, S->bsum, NV_ALL);
    k_fill_all<<<ceil_div(Ttot, 256), 256>>>(
        e_cr, e_cr + Ecr, Ecr, NA, O0,
        e_in, e_in + Ein, Ein, NW, O1,
        e_cb, e_cb + Ecb, Ecb, NA, O2,
        e_co, e_co + Eco, Eco, NA, O3,
        S->cursor, S->csr);

    // ---- artist MLP ----
    tg(S->afhl, nullptr, S->Bt_aw1, nullptr, a_b1, nullptr, S->hidA,
       nullptr, nullptr, nullptr, NA, 64, 128, 1);
    tg(S->hidA, nullptr, S->Bt_aw2, nullptr, a_b2, nullptr, S->axhl,
       S->u_cr, nullptr, S->ddA, NA, 128, 128, 0);

    // ---- work MLP folded: ddW only ----
    tg(S->wfhl, nullptr, S->Bt_ww1, nullptr, w_b1, nullptr, nullptr,
       S->v2, &S->c0, S->ddW, NW, 128, 128, 1);

    // ---- GAT1: creates (artist -> work), ELU ----
    tg(S->axhl, nullptr, S->Bt_crW, nullptr, nullptr, S->hsA, nullptr,
       cr_as, nullptr, S->s, NA, 128, 128, 0);
    gat(O0, S->hsA, S->ddW, cr_b, S->wx1hl, NW, 1, S->u_in, S->dd2);

    // ---- GAT2: infl (work -> work), ELU ----
    tg(S->wx1hl, nullptr, S->Bt_inW, nullptr, nullptr, S->hsW, nullptr,
       in_as, nullptr, S->s, NW, 128, 128, 0);
    gat(O1, S->hsW, S->dd2, in_b, S->wx2hl, NW, 1, nullptr, nullptr);

    // ---- GAT3: created_by (work -> artist), no act ----
    tg(S->wx2hl, nullptr, S->Bt_crW, nullptr, nullptr, S->hsW, nullptr,
       cr_as, nullptr, S->s, NW, 128, 128, 0);
    gat(O2, S->hsW, S->ddA, cr_b, S->auhl, NA, 0, S->u_co, S->dd3);

    // ---- GAT4: collab (artist -> artist), ELU ----
    tg(S->auhl, nullptr, S->Bt_coW, nullptr, nullptr, S->hsA, nullptr,
       co_as, nullptr, S->s, NA, 128, 128, 0);
    gat(O3, S->hsA, S->dd3, co_b, S->achl, NA, 1, nullptr, nullptr);

    // ---- predictor ----
    tg(S->auhl, S->achl, S->Bt_pw1a, S->Bt_pw1b, p_b1, nullptr, S->h1hl,
       nullptr, nullptr, nullptr, NA, 128, 256, 1);
    tg(S->h1hl, nullptr, S->Bt_pw2, nullptr, p_b2, nullptr, nullptr,
       p_w3, p_b3, out, NA, 256, 128, 1);
}

// round 17
// speedup vs baseline: 1.8596x; 1.0501x over previous
#include <cuda_runtime.h>
#include <cuda_bf16.h>
#include <cuda_fp16.h>
#include <cstdint>
#include <math.h>

#define NA 20000
#define NW 100000
#define HD 128
#define NV_ALL (2 * NW + 2 * NA)     // 240000
#define CSR_ALL 2000000

// ===========================================================================
// Scratch
// ===========================================================================
struct Scratch {
    __nv_bfloat16 afhl[NA * 128];
    __nv_bfloat16 wfhl[(size_t)NW * 256];
    __nv_bfloat16 hidA[NA * 256];
    __nv_bfloat16 axhl[NA * 256];
    __nv_bfloat16 wx1hl[(size_t)NW * 256];
    __nv_bfloat16 wx2hl[(size_t)NW * 256];
    __nv_bfloat16 auhl[NA * 256];
    __nv_bfloat16 achl[NA * 256];
    __nv_bfloat16 h1hl[NA * 512];
    __nv_bfloat16 Bt_aw1[128 * 128];
    __nv_bfloat16 Bt_aw2[128 * 256];
    __nv_bfloat16 Bt_ww1[128 * 256];
    __nv_bfloat16 Bt_crW[128 * 256];
    __nv_bfloat16 Bt_inW[128 * 256];
    __nv_bfloat16 Bt_coW[128 * 256];
    __nv_bfloat16 Bt_pw1a[256 * 256];
    __nv_bfloat16 Bt_pw1b[256 * 256];
    __nv_bfloat16 Bt_pw2[128 * 512];
    __half hsA[NA * HD];                 // fp16 hs (gather operand)
    __half hsW[(size_t)NW * HD];
    float s[NW];
    float ddW[NW];
    float dd2[NW];
    float ddA[NA];
    float dd3[NA];
    float u_cr[HD];
    float u_in[HD];
    float u_co[HD];
    float v2[HD];
    float c0;
    int cnt[NV_ALL];
    int indptr[NV_ALL + 1];
    int cursor[NV_ALL];
    int csr[CSR_ALL];
    int bsum[1024];
};
__device__ Scratch g_S;

// ===========================================================================
// PTX helpers (portable ISA only)
// ===========================================================================
__device__ __forceinline__ void cp_async16(uint32_t dst, const void* src) {
    asm volatile("cp.async.cg.shared.global [%0], [%1], 16;\n" :: "r"(dst), "l"(src));
}
__device__ __forceinline__ void cp_commit() { asm volatile("cp.async.commit_group;\n"); }
__device__ __forceinline__ void cp_wait0()  { asm volatile("cp.async.wait_group 0;\n"); }
__device__ __forceinline__ void cp_wait1()  { asm volatile("cp.async.wait_group 1;\n"); }

#define SWZ(off) ((off) ^ (((off) >> 3) & 0x70))

__device__ __forceinline__ void ldmx4(uint32_t& r0, uint32_t& r1, uint32_t& r2,
                                      uint32_t& r3, uint32_t addr) {
    asm volatile("ldmatrix.sync.aligned.m8n8.x4.shared.b16 {%0,%1,%2,%3}, [%4];"
                 : "=r"(r0), "=r"(r1), "=r"(r2), "=r"(r3) : "r"(addr));
}

__device__ __forceinline__ void mma16816(float* d, uint32_t a0, uint32_t a1,
                                         uint32_t a2, uint32_t a3,
                                         uint32_t b0, uint32_t b1) {
    asm volatile(
        "mma.sync.aligned.m16n8k16.row.col.f32.bf16.bf16.f32 "
        "{%0,%1,%2,%3}, {%4,%5,%6,%7}, {%8,%9}, {%0,%1,%2,%3};"
        : "+f"(d[0]), "+f"(d[1]), "+f"(d[2]), "+f"(d[3])
        : "r"(a0), "r"(a1), "r"(a2), "r"(a3), "r"(b0), "r"(b1));
}

// ===========================================================================
// HMMA GEMM.  Outputs: Ch fp16 (hs gather operand) and/or Chl bf16 hi|lo;
// fused row-dot sout = C_row . sv + (*svc).
// ===========================================================================
__global__ __launch_bounds__(256)
void k_tgemm(const __nv_bfloat16* __restrict__ A, const __nv_bfloat16* __restrict__ A2,
             const __nv_bfloat16* __restrict__ Bt, const __nv_bfloat16* __restrict__ Bt2,
             const float* __restrict__ bias,
             __half* __restrict__ Ch, __nv_bfloat16* __restrict__ Chl,
             const float* __restrict__ sv, const float* __restrict__ svc,
             float* __restrict__ sout,
             int M, int K, int n, int act)
{
    extern __shared__ char sh[];
    const uint32_t sb = (uint32_t)__cvta_generic_to_shared(sh);
    const uint32_t A_OFF = 0, B_OFF = 32768;

    const int tid = threadIdx.x, wid = tid >> 5, lane = tid & 31;
    const int row0 = blockIdx.x * 128, col0 = blockIdx.y * 128;

    const int KB = K >> 6;
    const int Thalf = 3 * KB;
    const int T = A2 ? 2 * Thalf : Thalf;
    const size_t rs = (size_t)2 * K;

    float d[16][4];
#pragma unroll
    for (int i = 0; i < 16; i++)
#pragma unroll
        for (int j = 0; j < 4; j++) d[i][j] = 0.f;

    auto issue = [&](int t) {
        int b = t & 1;
        int tt = t;
        const __nv_bfloat16 *Ab = A, *Bb = Bt;
        if (A2 && tt >= Thalf) { tt -= Thalf; Ab = A2; Bb = Bt2; }
        const int phase = tt / KB;
        const int kb = tt - phase * KB;
        const int aoff = ((phase == 1) ? K : 0) + kb * 64;
        const int boff = ((phase == 2) ? K : 0) + kb * 64;
#pragma unroll
        for (int i = 0; i < 4; i++) {
            int idx = tid + i * 256;
            int r = idx >> 3, u = idx & 7;
            uint32_t sw = SWZ((uint32_t)(r * 128 + u * 16));
            cp_async16(sb + B_OFF + b * 16384 + sw,
                       Bb + (size_t)(col0 + r) * rs + boff + u * 8);
            int gr = row0 + r;
            if (gr < M)
                cp_async16(sb + A_OFF + b * 16384 + sw,
                           Ab + (size_t)gr * rs + aoff + u * 8);
            else
                *(uint4*)(sh + A_OFF + b * 16384 + sw) = make_uint4(0, 0, 0, 0);
        }
        cp_commit();
    };

    const int g = lane >> 3, lr = lane & 7;
    const int m0 = wid * 16;

    issue(0);
    for (int t = 0; t < T; t++) {
        if (t + 1 < T) { issue(t + 1); cp_wait1(); } else { cp_wait0(); }
        __syncthreads();

        const uint32_t sA = sb + A_OFF + (t & 1) * 16384;
        const uint32_t sB = sb + B_OFF + (t & 1) * 16384;
        const int arow = m0 + lr + ((g & 1) << 3);
        const int brow_lo = (g >> 1) * 8 + lr;
#pragma unroll
        for (int ks = 0; ks < 4; ks++) {
            uint32_t a0, a1, a2, a3;
            int akblk = ks * 2 + (g >> 1);
            ldmx4(a0, a1, a2, a3, sA + SWZ((uint32_t)(arow * 128 + akblk * 16)));
            int bkblk = ks * 2 + (g & 1);
#pragma unroll
            for (int jp = 0; jp < 8; jp++) {
                uint32_t b0, b1, b2, b3;
                int nrow = jp * 16 + brow_lo;
                ldmx4(b0, b1, b2, b3, sB + SWZ((uint32_t)(nrow * 128 + bkblk * 16)));
                mma16816(d[jp * 2], a0, a1, a2, a3, b0, b1);
                mma16816(d[jp * 2 + 1], a0, a1, a2, a3, b2, b3);
            }
        }
        __syncthreads();
    }

    const int r0 = row0 + m0 + (lane >> 2);
    const int r1 = r0 + 8;
    float p0 = 0.f, p1 = 0.f;
#pragma unroll
    for (int nf = 0; nf < 16; nf++) {
        int gc = col0 + nf * 8 + (lane & 3) * 2;
        float v00 = d[nf][0], v01 = d[nf][1], v10 = d[nf][2], v11 = d[nf][3];
        if (bias) {
            float b0 = __ldg(bias + gc), b1 = __ldg(bias + gc + 1);
            v00 += b0; v01 += b1; v10 += b0; v11 += b1;
        }
        if (act == 1) {
            v00 = fmaxf(v00, 0.f); v01 = fmaxf(v01, 0.f);
            v10 = fmaxf(v10, 0.f); v11 = fmaxf(v11, 0.f);
        }
        if (sv) {
            float s0 = __ldg(sv + gc), s1 = __ldg(sv + gc + 1);
            p0 = fmaf(v00, s0, fmaf(v01, s1, p0));
            p1 = fmaf(v10, s0, fmaf(v11, s1, p1));
        }
        if (Ch) {
            if (r0 < M) *(__half2*)(Ch + (size_t)r0 * n + gc) = __floats2half2_rn(v00, v01);
            if (r1 < M) *(__half2*)(Ch + (size_t)r1 * n + gc) = __floats2half2_rn(v10, v11);
        }
        if (Chl) {
            if (r0 < M) {
                __nv_bfloat16 h0 = __float2bfloat16(v00), h1 = __float2bfloat16(v01);
                __nv_bfloat162 hp = __halves2bfloat162(h0, h1);
                __nv_bfloat162 lp = __halves2bfloat162(
                    __float2bfloat16(v00 - __bfloat162float(h0)),
                    __float2bfloat16(v01 - __bfloat162float(h1)));
                *(__nv_bfloat162*)(Chl + (size_t)r0 * 2 * n + gc) = hp;
                *(__nv_bfloat162*)(Chl + (size_t)r0 * 2 * n + n + gc) = lp;
            }
            if (r1 < M) {
                __nv_bfloat16 h0 = __float2bfloat16(v10), h1 = __float2bfloat16(v11);
                __nv_bfloat162 hp = __halves2bfloat162(h0, h1);
                __nv_bfloat162 lp = __halves2bfloat162(
                    __float2bfloat16(v10 - __bfloat162float(h0)),
                    __float2bfloat16(v11 - __bfloat162float(h1)));
                *(__nv_bfloat162*)(Chl + (size_t)r1 * 2 * n + gc) = hp;
                *(__nv_bfloat162*)(Chl + (size_t)r1 * 2 * n + n + gc) = lp;
            }
        }
    }
    if (sv) {
        p0 += __shfl_xor_sync(0xffffffffu, p0, 1);
        p0 += __shfl_xor_sync(0xffffffffu, p0, 2);
        p1 += __shfl_xor_sync(0xffffffffu, p1, 1);
        p1 += __shfl_xor_sync(0xffffffffu, p1, 2);
        if ((lane & 3) == 0) {
            float c = svc ? *svc : 0.f;
            if (r0 < M) sout[r0] = p0 + c;
            if (r1 < M) sout[r1] = p1 + c;
        }
    }
}

// ===========================================================================
// Prelude matvecs
// ===========================================================================
__global__ void k_mv3(const float* __restrict__ W0, const float* __restrict__ v0,
                      float* __restrict__ u0,
                      const float* __restrict__ W1, const float* __restrict__ v1,
                      float* __restrict__ u1,
                      const float* __restrict__ W2, const float* __restrict__ v2,
                      float* __restrict__ u2)
{
    const float* W; const float* v; float* u;
    if (blockIdx.y == 0) { W = W0; v = v0; u = u0; }
    else if (blockIdx.y == 1) { W = W1; v = v1; u = u1; }
    else { W = W2; v = v2; u = u2; }
    int wid = threadIdx.x >> 5, lane = threadIdx.x & 31;
    int row = blockIdx.x * 8 + wid;
    float sm = 0.f;
#pragma unroll
    for (int c = lane; c < 128; c += 32) sm = fmaf(W[row * 128 + c], v[c], sm);
#pragma unroll
    for (int off = 16; off; off >>= 1) sm += __shfl_xor_sync(0xffffffffu, sm, off);
    if (lane == 0) u[row] = sm;
}

__global__ void k_mv2(const float* __restrict__ w_w2, const float* __restrict__ u_cr,
                      float* __restrict__ v2,
                      const float* __restrict__ w_b2, float* __restrict__ c0)
{
    if (blockIdx.x < 16) {
        int wid = threadIdx.x >> 5, lane = threadIdx.x & 31;
        int row = blockIdx.x * 8 + wid;
        float sm = 0.f;
#pragma unroll
        for (int c = lane; c < 128; c += 32) sm = fmaf(w_w2[row * 128 + c], u_cr[c], sm);
#pragma unroll
        for (int off = 16; off; off >>= 1) sm += __shfl_xor_sync(0xffffffffu, sm, off);
        if (lane == 0) v2[row] = sm;
    } else {
        __shared__ float red[4];
        int t = threadIdx.x;
        float v = (t < 128) ? w_b2[t] * u_cr[t] : 0.f;
#pragma unroll
        for (int off = 16; off; off >>= 1) v += __shfl_xor_sync(0xffffffffu, v, off);
        if ((t & 31) == 0) red[t >> 5] = v;
        __syncthreads();
        if (t == 0) c0[0] = red[0] + red[1] + red[2] + red[3];
    }
}

// ===========================================================================
// Conversions (vectorized, division-free)
// ===========================================================================
template<int K>
__global__ void k_cvtA4(const float* __restrict__ X, __nv_bfloat16* __restrict__ Y,
                        int M)
{
    constexpr int KQ = K / 4;
    int i4 = blockIdx.x * 256 + threadIdx.x;
    if (i4 >= M * KQ) return;
    int m = i4 / KQ;
    int kq = i4 - m * KQ;
    float4 x = ((const float4*)X)[i4];
    __nv_bfloat16 h0 = __float2bfloat16(x.x), h1 = __float2bfloat16(x.y);
    __nv_bfloat16 h2 = __float2bfloat16(x.z), h3 = __float2bfloat16(x.w);
    __nv_bfloat162 hp0 = __halves2bfloat162(h0, h1);
    __nv_bfloat162 hp1 = __halves2bfloat162(h2, h3);
    __nv_bfloat162 lp0 = __halves2bfloat162(
        __float2bfloat16(x.x - __bfloat162float(h0)),
        __float2bfloat16(x.y - __bfloat162float(h1)));
    __nv_bfloat162 lp1 = __halves2bfloat162(
        __float2bfloat16(x.z - __bfloat162float(h2)),
        __float2bfloat16(x.w - __bfloat162float(h3)));
    uint2 hv = make_uint2(*(uint32_t*)&hp0, *(uint32_t*)&hp1);
    uint2 lv = make_uint2(*(uint32_t*)&lp0, *(uint32_t*)&lp1);
    ((uint2*)(Y + (size_t)m * 2 * K))[kq] = hv;
    ((uint2*)(Y + (size_t)m * 2 * K + K))[kq] = lv;
}

struct CvtJobs {
    const float* src[9];
    __nv_bfloat16* dst[9];
    int K[9], n[9];
};

__global__ void k_cvtW(CvtJobs J)
{
    int g = blockIdx.y;
    int K = J.K[g], n = J.n[g];
    int i = blockIdx.x * 256 + threadIdx.x;
    if (i >= K * n) return;
    int k = i / n, c = i % n;
    float x = J.src[g][i];
    __nv_bfloat16 h = __float2bfloat16(x);
    __nv_bfloat16 l = __float2bfloat16(x - __bfloat162float(h));
    J.dst[g][(size_t)c * 2 * K + k] = h;
    J.dst[g][(size_t)c * 2 * K + K + k] = l;
}

// ===========================================================================
// Unified CSR build
// ===========================================================================
__global__ void k_count_all(const int* __restrict__ d0, int E0, int L0, int o0,
                            const int* __restrict__ d1, int E1, int L1, int o1,
                            const int* __restrict__ d2, int E2, int L2, int o2,
                            const int* __restrict__ d3, int E3, int L3, int o3,
                            int* __restrict__ cnt)
{
    int i = blockIdx.x * 256 + threadIdx.x;
    int T0 = E0 + L0, T1 = E1 + L1, T2 = E2 + L2, T3 = E3 + L3;
    if (i < T0) { atomicAdd(cnt + o0 + ((i < E0) ? d0[i] : i - E0), 1); return; }
    i -= T0;
    if (i < T1) { atomicAdd(cnt + o1 + ((i < E1) ? d1[i] : i - E1), 1); return; }
    i -= T1;
    if (i < T2) { atomicAdd(cnt + o2 + ((i < E2) ? d2[i] : i - E2), 1); return; }
    i -= T2;
    if (i < T3) { atomicAdd(cnt + o3 + ((i < E3) ? d3[i] : i - E3), 1); }
}

__global__ void k_fill_all(const int* __restrict__ s0, const int* __restrict__ d0,
                           int E0, int L0, int o0,
                           const int* __restrict__ s1, const int* __restrict__ d1,
                           int E1, int L1, int o1,
                           const int* __restrict__ s2, const int* __restrict__ d2,
                           int E2, int L2, int o2,
                           const int* __restrict__ s3, const int* __restrict__ d3,
                           int E3, int L3, int o3,
                           int* __restrict__ cursor, int* __restrict__ csr)
{
    int i = blockIdx.x * 256 + threadIdx.x;
    int T0 = E0 + L0, T1 = E1 + L1, T2 = E2 + L2, T3 = E3 + L3;
    const int* sp; const int* dp; int E, off;
    if (i < T0) { sp = s0; dp = d0; E = E0; off = o0; }
    else {
        i -= T0;
        if (i < T1) { sp = s1; dp = d1; E = E1; off = o1; }
        else {
            i -= T1;
            if (i < T2) { sp = s2; dp = d2; E = E2; off = o2; }
            else {
                i -= T2;
                if (i >= T3) return;
                sp = s3; dp = d3; E = E3; off = o3;
            }
        }
    }
    int dst = (i < E) ? dp[i] : i - E;
    int src = (i < E) ? sp[i] : i - E;
    int p = atomicAdd(cursor + off + dst, 1);
    csr[p] = src;
}

__global__ void k_scan_block(const int* __restrict__ in, int* __restrict__ out,
                             int* __restrict__ bsums, int nv)
{
    __shared__ int sh[1024];
    int i = blockIdx.x * 1024 + threadIdx.x;
    int v = (i < nv) ? in[i] : 0;
    sh[threadIdx.x] = v;
    __syncthreads();
    for (int off = 1; off < 1024; off <<= 1) {
        int t = (threadIdx.x >= off) ? sh[threadIdx.x - off] : 0;
        __syncthreads();
        sh[threadIdx.x] += t;
        __syncthreads();
    }
    if (i < nv) out[i] = sh[threadIdx.x] - v;
    if (threadIdx.x == 1023) bsums[blockIdx.x] = sh[1023];
}

__global__ void k_scan_bsums(int* __restrict__ bsums, int nb, int* __restrict__ total_out)
{
    __shared__ int sh[1024];
    int i = threadIdx.x;
    int v = (i < nb) ? bsums[i] : 0;
    sh[i] = v;
    __syncthreads();
    for (int off = 1; off < 1024; off <<= 1) {
        int t = (i >= off) ? sh[i - off] : 0;
        __syncthreads();
        sh[i] += t;
        __syncthreads();
    }
    if (i < nb) bsums[i] = sh[i] - v;
    if (i == nb - 1) *total_out = sh[i];
}

__global__ void k_scan_add(int* __restrict__ indptr, int* __restrict__ cursor,
                           const int* __restrict__ bsums, int nv)
{
    int i = blockIdx.x * blockDim.x + threadIdx.x;
    if (i < nv) {
        int v = indptr[i] + bsums[i >> 10];
        indptr[i] = v;
        cursor[i] = v;
    }
}

// ===========================================================================
// GAT aggregation: warp/dst; hs is fp16 (8B/lane loads).  deg<=32 fast path.
// ===========================================================================
__device__ __forceinline__ void hs_load_acc(const __half* __restrict__ hs,
                                            int sn, int lane, float wt, float4& acc)
{
    uint2 hvu = ((const uint2*)(hs + (size_t)sn * 128))[lane];
    __half2 h0 = *(__half2*)&hvu.x, h1 = *(__half2*)&hvu.y;
    float2 f0 = __half22float2(h0), f1 = __half22float2(h1);
    acc.x = fmaf(wt, f0.x, acc.x);
    acc.y = fmaf(wt, f0.y, acc.y);
    acc.z = fmaf(wt, f1.x, acc.z);
    acc.w = fmaf(wt, f1.y, acc.w);
}

__global__ void k_gat(const int* __restrict__ indptr, const int* __restrict__ csr,
                      int off,
                      const __half* __restrict__ hs, const float* __restrict__ s,
                      const float* __restrict__ d, const float* __restrict__ bias,
                      __nv_bfloat16* __restrict__ ohl, int ndst, int act,
                      const float* __restrict__ unext, float* __restrict__ dd_out)
{
    int w = (blockIdx.x * blockDim.x + threadIdx.x) >> 5;
    int lane = threadIdx.x & 31;
    if (w >= ndst) return;

    int beg = indptr[off + w], end = indptr[off + w + 1];
    int deg = end - beg;
    float4 b4 = ((const float4*)bias)[lane];
    float4 o;

    if (deg == 0) {
        o = b4;
    } else if (deg <= 32) {
        float dj = d[w];
        int sn = 0;
        float l = -3.0e38f;
        if (lane < deg) {
            sn = csr[beg + lane];
            float t = s[sn] + dj;
            l = (t > 0.f) ? t : 0.2f * t;
        }
        float m = l;
#pragma unroll
        for (int o2 = 16; o2; o2 >>= 1)
            m = fmaxf(m, __shfl_xor_sync(0xffffffffu, m, o2));
        float wt = (lane < deg) ? __expf(l - m) : 0.f;
        float denom = wt;
#pragma unroll
        for (int o2 = 16; o2; o2 >>= 1)
            denom += __shfl_xor_sync(0xffffffffu, denom, o2);
        float4 acc = make_float4(0.f, 0.f, 0.f, 0.f);
        for (int j = 0; j < deg; j++) {
            int snj = __shfl_sync(0xffffffffu, sn, j);
            float wtj = __shfl_sync(0xffffffffu, wt, j);
            hs_load_acc(hs, snj, lane, wtj, acc);
        }
        float inv = 1.0f / denom;
        o.x = fmaf(acc.x, inv, b4.x);
        o.y = fmaf(acc.y, inv, b4.y);
        o.z = fmaf(acc.z, inv, b4.z);
        o.w = fmaf(acc.w, inv, b4.w);
    } else {
        float dj = d[w];
        float m = -3.0e38f;
        for (int e = beg + lane; e < end; e += 32) {
            float l = s[csr[e]] + dj;
            l = (l > 0.f) ? l : 0.2f * l;
            m = fmaxf(m, l);
        }
#pragma unroll
        for (int o2 = 16; o2; o2 >>= 1)
            m = fmaxf(m, __shfl_xor_sync(0xffffffffu, m, o2));

        float denom = 0.f;
        float4 acc = make_float4(0.f, 0.f, 0.f, 0.f);
        for (int e = beg; e < end; e++) {
            int sn = csr[e];
            float l = s[sn] + dj;
            l = (l > 0.f) ? l : 0.2f * l;
            float wt = __expf(l - m);
            denom += wt;
            hs_load_acc(hs, sn, lane, wt, acc);
        }
        float inv = 1.0f / denom;
        o.x = fmaf(acc.x, inv, b4.x);
        o.y = fmaf(acc.y, inv, b4.y);
        o.z = fmaf(acc.z, inv, b4.z);
        o.w = fmaf(acc.w, inv, b4.w);
    }

    if (act == 1) {
        o.x = (o.x > 0.f) ? o.x : expm1f(o.x);
        o.y = (o.y > 0.f) ? o.y : expm1f(o.y);
        o.z = (o.z > 0.f) ? o.z : expm1f(o.z);
        o.w = (o.w > 0.f) ? o.w : expm1f(o.w);
    }

    __nv_bfloat16 hx = __float2bfloat16(o.x), hy = __float2bfloat16(o.y);
    __nv_bfloat16 hz = __float2bfloat16(o.z), hw = __float2bfloat16(o.w);
    __nv_bfloat16 lx = __float2bfloat16(o.x - __bfloat162float(hx));
    __nv_bfloat16 ly = __float2bfloat16(o.y - __bfloat162float(hy));
    __nv_bfloat16 lz = __float2bfloat16(o.z - __bfloat162float(hz));
    __nv_bfloat16 lw = __float2bfloat16(o.w - __bfloat162float(hw));
    __nv_bfloat162 h01 = __halves2bfloat162(hx, hy), h23 = __halves2bfloat162(hz, hw);
    __nv_bfloat162 l01 = __halves2bfloat162(lx, ly), l23 = __halves2bfloat162(lz, lw);
    uint2 hv2 = make_uint2(*(uint32_t*)&h01, *(uint32_t*)&h23);
    uint2 lv2 = make_uint2(*(uint32_t*)&l01, *(uint32_t*)&l23);
    ((uint2*)(ohl + (size_t)w * 256))[lane] = hv2;
    ((uint2*)(ohl + (size_t)w * 256 + 128))[lane] = lv2;

    if (dd_out) {
        float4 u4 = ((const float4*)unext)[lane];
        float p = o.x * u4.x + o.y * u4.y + o.z * u4.z + o.w * u4.w;
#pragma unroll
        for (int o2 = 16; o2; o2 >>= 1) p += __shfl_xor_sync(0xffffffffu, p, o2);
        if (lane == 0) dd_out[w] = p;
    }
}

// ===========================================================================
static inline int ceil_div(int a, int b) { return (a + b - 1) / b; }
static const int TG_SMEM = 65536;

extern "C" void kernel_launch(void* const* d_in, const int* in_sizes, int n_in,
                              void* d_out, int out_size)
{
    Scratch* S;
    cudaGetSymbolAddress((void**)&S, g_S);
    cudaFuncSetAttribute(k_tgemm, cudaFuncAttributeMaxDynamicSharedMemorySize, TG_SMEM);

    const float* af   = (const float*)d_in[0];
    const float* wf   = (const float*)d_in[1];
    const float* a_w1 = (const float*)d_in[2];
    const float* a_b1 = (const float*)d_in[3];
    const float* a_w2 = (const float*)d_in[4];
    const float* a_b2 = (const float*)d_in[5];
    const float* w_w1 = (const float*)d_in[6];
    const float* w_b1 = (const float*)d_in[7];
    const float* w_w2 = (const float*)d_in[8];
    const float* w_b2 = (const float*)d_in[9];
    const float* cr_W = (const float*)d_in[10];
    const float* cr_b = (const float*)d_in[11];
    const float* cr_as = (const float*)d_in[12];
    const float* cr_ad = (const float*)d_in[13];
    const float* in_W = (const float*)d_in[14];
    const float* in_b = (const float*)d_in[15];
    const float* in_as = (const float*)d_in[16];
    const float* in_ad = (const float*)d_in[17];
    const float* co_W = (const float*)d_in[18];
    const float* co_b = (const float*)d_in[19];
    const float* co_as = (const float*)d_in[20];
    const float* co_ad = (const float*)d_in[21];
    const float* p_w1 = (const float*)d_in[22];
    const float* p_b1 = (const float*)d_in[23];
    const float* p_w2 = (const float*)d_in[24];
    const float* p_b2 = (const float*)d_in[25];
    const float* p_w3 = (const float*)d_in[26];
    const float* p_b3 = (const float*)d_in[27];
    const int* e_cr = (const int*)d_in[28]; int Ecr = in_sizes[28] / 2;
    const int* e_cb = (const int*)d_in[29]; int Ecb = in_sizes[29] / 2;
    const int* e_in = (const int*)d_in[30]; int Ein = in_sizes[30] / 2;
    const int* e_co = (const int*)d_in[31]; int Eco = in_sizes[31] / 2;
    float* out = (float*)d_out;

    const int O0 = 0, O1 = NW, O2 = 2 * NW, O3 = 2 * NW + NA;

    auto tg = [&](const __nv_bfloat16* A, const __nv_bfloat16* A2,
                  const __nv_bfloat16* Bt, const __nv_bfloat16* Bt2,
                  const float* bias, __half* Ch, __nv_bfloat16* Chl,
                  const float* sv, const float* svc, float* sout,
                  int M, int K, int n, int act) {
        dim3 g(ceil_div(M, 128), n / 128);
        k_tgemm<<<g, 256, TG_SMEM>>>(A, A2, Bt, Bt2, bias, Ch, Chl, sv, svc, sout,
                                     M, K, n, act);
    };
    auto gat = [&](int off, const __half* hs, const float* d, const float* bias,
                   __nv_bfloat16* ohl, int ndst, int act,
                   const float* unext, float* dd_out) {
        k_gat<<<ceil_div(ndst, 8), 256>>>(S->indptr, S->csr, off, hs, S->s, d,
                                          bias, ohl, ndst, act, unext, dd_out);
    };

    // ---- prelude: u vectors + folded work-MLP projection ----
    k_mv3<<<dim3(16, 3), 256>>>(cr_W, cr_ad, S->u_cr,
                                in_W, in_ad, S->u_in,
                                co_W, co_ad, S->u_co);
    k_mv2<<<17, 256>>>(w_w2, S->u_cr, S->v2, w_b2, &S->c0);

    // ---- feature + weight conversions ----
    k_cvtA4<64><<<ceil_div(NA * 16, 256), 256>>>(af, S->afhl, NA);
    k_cvtA4<128><<<ceil_div(NW * 32, 256), 256>>>(wf, S->wfhl, NW);
    {
        CvtJobs J;
        J.src[0] = a_w1; J.dst[0] = S->Bt_aw1;  J.K[0] = 64;  J.n[0] = 128;
        J.src[1] = a_w2; J.dst[1] = S->Bt_aw2;  J.K[1] = 128; J.n[1] = 128;
        J.src[2] = w_w1; J.dst[2] = S->Bt_ww1;  J.K[2] = 128; J.n[2] = 128;
        J.src[3] = cr_W; J.dst[3] = S->Bt_crW;  J.K[3] = 128; J.n[3] = 128;
        J.src[4] = in_W; J.dst[4] = S->Bt_inW;  J.K[4] = 128; J.n[4] = 128;
        J.src[5] = co_W; J.dst[5] = S->Bt_coW;  J.K[5] = 128; J.n[5] = 128;
        J.src[6] = p_w1;             J.dst[6] = S->Bt_pw1a; J.K[6] = 128; J.n[6] = 256;
        J.src[7] = p_w1 + 128 * 256; J.dst[7] = S->Bt_pw1b; J.K[7] = 128; J.n[7] = 256;
        J.src[8] = p_w2;             J.dst[8] = S->Bt_pw2;  J.K[8] = 256; J.n[8] = 128;
        k_cvtW<<<dim3(128, 9), 256>>>(J);
    }

    // ---- unified CSR build ----
    cudaMemsetAsync(S->cnt, 0, NV_ALL * sizeof(int));
    int Ttot = (Ecr + NA) + (Ein + NW) + (Ecb + NA) + (Eco + NA);
    k_count_all<<<ceil_div(Ttot, 256), 256>>>(
        e_cr + Ecr, Ecr, NA, O0,
        e_in + Ein, Ein, NW, O1,
        e_cb + Ecb, Ecb, NA, O2,
        e_co + Eco, Eco, NA, O3, S->cnt);
    int nb = ceil_div(NV_ALL, 1024);
    k_scan_block<<<nb, 1024>>>(S->cnt, S->indptr, S->bsum, NV_ALL);
    k_scan_bsums<<<1, 1024>>>(S->bsum, nb, S->indptr + NV_ALL);
    k_scan_add<<<ceil_div(NV_ALL, 256), 256>>>(S->indptr, S->cursor, S->bsum, NV_ALL);
    k_fill_all<<<ceil_div(Ttot, 256), 256>>>(
        e_cr, e_cr + Ecr, Ecr, NA, O0,
        e_in, e_in + Ein, Ein, NW, O1,
        e_cb, e_cb + Ecb, Ecb, NA, O2,
        e_co, e_co + Eco, Eco, NA, O3,
        S->cursor, S->csr);

    // ---- artist MLP ----
    tg(S->afhl, nullptr, S->Bt_aw1, nullptr, a_b1, nullptr, S->hidA,
       nullptr, nullptr, nullptr, NA, 64, 128, 1);
    tg(S->hidA, nullptr, S->Bt_aw2, nullptr, a_b2, nullptr, S->axhl,
       S->u_cr, nullptr, S->ddA, NA, 128, 128, 0);

    // ---- work MLP folded: ddW only ----
    tg(S->wfhl, nullptr, S->Bt_ww1, nullptr, w_b1, nullptr, nullptr,
       S->v2, &S->c0, S->ddW, NW, 128, 128, 1);

    // ---- GAT1: creates (artist -> work), ELU ----
    tg(S->axhl, nullptr, S->Bt_crW, nullptr, nullptr, S->hsA, nullptr,
       cr_as, nullptr, S->s, NA, 128, 128, 0);
    gat(O0, S->hsA, S->ddW, cr_b, S->wx1hl, NW, 1, S->u_in, S->dd2);

    // ---- GAT2: infl (work -> work), ELU ----
    tg(S->wx1hl, nullptr, S->Bt_inW, nullptr, nullptr, S->hsW, nullptr,
       in_as, nullptr, S->s, NW, 128, 128, 0);
    gat(O1, S->hsW, S->dd2, in_b, S->wx2hl, NW, 1, nullptr, nullptr);

    // ---- GAT3: created_by (work -> artist), no act ----
    tg(S->wx2hl, nullptr, S->Bt_crW, nullptr, nullptr, S->hsW, nullptr,
       cr_as, nullptr, S->s, NW, 128, 128, 0);
    gat(O2, S->hsW, S->ddA, cr_b, S->auhl, NA, 0, S->u_co, S->dd3);

    // ---- GAT4: collab (artist -> artist), ELU ----
    tg(S->auhl, nullptr, S->Bt_coW, nullptr, nullptr, S->hsA, nullptr,
       co_as, nullptr, S->s, NA, 128, 128, 0);
    gat(O3, S->hsA, S->dd3, co_b, S->achl, NA, 1, nullptr, nullptr);

    // ---- predictor ----
    tg(S->auhl, S->achl, S->Bt_pw1a, S->Bt_pw1b, p_b1, nullptr, S->h1hl,
       nullptr, nullptr, nullptr, NA, 128, 256, 1);
    tg(S->h1hl, nullptr, S->Bt_pw2, nullptr, p_b2, nullptr, nullptr,
       p_w3, p_b3, out, NA, 256, 128, 1);
}